// round 13
// baseline (speedup 1.0000x reference)
#include <cuda_runtime.h>

// DeltaNet chunkwise delta rule.
// Shapes fixed by the problem: b=4, h=4, L=4096, dk=dv=256, chunk=32.

#define LSEQ  4096
#define DKV   256
#define CCH   32
#define NCH   (LSEQ / CCH)      // 128 chunks
#define BHT   16                // b*h
#define JBW   32                // dv block width
#define NJB   (DKV / JBW)       // 8 column blocks

#define OUT_ELEMS   ((size_t)BHT * LSEQ * DKV)        // 16777216
#define STATE_ELEMS ((size_t)BHT * DKV * DKV)         // 1048576

// Scratch (device globals; no allocation allowed)
__device__ float g_qn [(size_t)BHT * LSEQ * DKV];
__device__ float g_kn [(size_t)BHT * LSEQ * DKV];
__device__ float g_w  [(size_t)BHT * LSEQ * DKV];
__device__ float g_u  [(size_t)BHT * LSEQ * DKV];
__device__ float g_att[(size_t)BHT * NCH * CCH * CCH];
// Per-chunk state snapshots S_ch ([j][d] slices) and UADJ, consumed by phase3.
__device__ float g_S   [(size_t)NCH * BHT * NJB * DKV * JBW];   // 512 MB
__device__ float g_uadj[(size_t)NCH * BHT * NJB * CCH * JBW];   // 64 MB

// ---- packed f32x2 helpers (2x FFMA throughput vs 3-reg FFMA on sm_103a) ----
__device__ __forceinline__ unsigned long long ffma2(unsigned long long a,
                                                    unsigned long long b,
                                                    unsigned long long c) {
    unsigned long long d;
    asm("fma.rn.f32x2 %0, %1, %2, %3;" : "=l"(d) : "l"(a), "l"(b), "l"(c));
    return d;
}
__device__ __forceinline__ unsigned long long splat2(float x) {
    unsigned long long d;
    unsigned int r = __float_as_uint(x);
    asm("mov.b64 %0, {%1, %1};" : "=l"(d) : "r"(r));
    return d;
}
__device__ __forceinline__ float fold2(unsigned long long a) {
    unsigned int lo, hi;
    asm("mov.b64 {%0, %1}, %2;" : "=r"(lo), "=r"(hi) : "l"(a));
    return __uint_as_float(lo) + __uint_as_float(hi);
}

// ---- cp.async: global -> shared 16B, no register round-trip ----
__device__ __forceinline__ void cpa16(void* smem_dst, const void* gmem_src) {
    unsigned int s = (unsigned int)__cvta_generic_to_shared(smem_dst);
    asm volatile("cp.async.ca.shared.global [%0], [%1], 16;" :: "r"(s), "l"(gmem_src));
}
__device__ __forceinline__ void cpa_commit() {
    asm volatile("cp.async.commit_group;");
}
__device__ __forceinline__ void cpa_wait_all() {
    asm volatile("cp.async.wait_group 0;" ::: "memory");
}

// ============================================================================
// Phase 1: per-chunk preprocessing (parallel over bh * chunks = 2048 CTAs).
// ============================================================================
#define P1S 260

__global__ __launch_bounds__(256, 2)
void phase1(const float* __restrict__ q, const float* __restrict__ k,
            const float* __restrict__ v, const float* __restrict__ beta)
{
    const int ch = blockIdx.x;
    const int bh = blockIdx.y;
    extern __shared__ float sm[];
    float* Q   = sm;                         // 32 * 260
    float* K   = Q + 32 * P1S;
    float* V   = K + 32 * P1S;
    float* A   = V + 32 * P1S;               // 32 * 36
    float* RED = A + 32 * 36;                // 512
    float* BET = RED + 512;                  // 32
    float* NRM = BET + 32;                   // 64

    const int t = threadIdx.x;
    const size_t base = ((size_t)bh * LSEQ + (size_t)ch * CCH) * DKV;
    const float4* q4 = (const float4*)(q + base);
    const float4* k4 = (const float4*)(k + base);
    const float4* v4 = (const float4*)(v + base);

#pragma unroll
    for (int r = 0; r < 8; r++) {
        int f   = t + r * 256;
        int row = f >> 6, c4 = f & 63;
        cpa16(&Q[row * P1S + c4 * 4], &q4[f]);
        cpa16(&K[row * P1S + c4 * 4], &k4[f]);
        cpa16(&V[row * P1S + c4 * 4], &v4[f]);
    }
    if (t < CCH) BET[t] = beta[(size_t)bh * LSEQ + ch * CCH + t];
    cpa_commit();
    cpa_wait_all();
    __syncthreads();

    // row sum-of-squares for q and k
    {
        int r = t >> 3, s = t & 7;
        float aq = 0.f, ak = 0.f;
#pragma unroll
        for (int m = 0; m < 32; m++) {
            float xq = Q[r * P1S + s * 32 + m];
            float xk = K[r * P1S + s * 32 + m];
            aq += xq * xq;
            ak += xk * xk;
        }
        RED[r * 8 + s]       = aq;
        RED[256 + r * 8 + s] = ak;
    }
    __syncthreads();
    if (t < 64) {
        int r = t & 31, wsel = t >> 5;
        float ssum = 0.f;
#pragma unroll
        for (int s = 0; s < 8; s++) ssum += RED[wsel * 256 + r * 8 + s];
        NRM[t] = rsqrtf(ssum);
    }
    __syncthreads();

    // normalize q,k (write qn,kn straight to global) ; v *= beta
    {
        float4* oq = (float4*)(g_qn + base);
        float4* ok = (float4*)(g_kn + base);
#pragma unroll
        for (int r = 0; r < 8; r++) {
            int f   = t + r * 256;
            int row = f >> 6, c4 = f & 63;
            float nq = NRM[row], nk = NRM[32 + row], be = BET[row];
            float4 xq = *(float4*)&Q[row * P1S + c4 * 4];
            xq.x *= nq; xq.y *= nq; xq.z *= nq; xq.w *= nq;
            *(float4*)&Q[row * P1S + c4 * 4] = xq;
            oq[f] = xq;
            float4 xk = *(float4*)&K[row * P1S + c4 * 4];
            xk.x *= nk; xk.y *= nk; xk.z *= nk; xk.w *= nk;
            *(float4*)&K[row * P1S + c4 * 4] = xk;
            ok[f] = xk;
            float4 xv = *(float4*)&V[row * P1S + c4 * 4];
            xv.x *= be; xv.y *= be; xv.z *= be; xv.w *= be;
            *(float4*)&V[row * P1S + c4 * 4] = xv;
        }
    }
    __syncthreads();

    // A (strict lower, beta_i * kn_i . kn_j) and att (tril incl diag).
    {
        const int w8 = t >> 5, la = t & 31;
        const int i  = w8 * 4 + (la >> 3);
        const int jq = la & 7;
        float dkk0 = 0.f, dkk1 = 0.f, dkk2 = 0.f, dkk3 = 0.f;
        float dqk0 = 0.f, dqk1 = 0.f, dqk2 = 0.f, dqk3 = 0.f;
        const float* Ki = &K[i * P1S];
        const float* Qi = &Q[i * P1S];
        const float* Kj0 = &K[(jq     ) * P1S];
        const float* Kj1 = &K[(jq +  8) * P1S];
        const float* Kj2 = &K[(jq + 16) * P1S];
        const float* Kj3 = &K[(jq + 24) * P1S];
#pragma unroll 8
        for (int d4 = 0; d4 < 64; d4++) {
            float4 ki = *(const float4*)&Ki[d4 * 4];
            float4 qi = *(const float4*)&Qi[d4 * 4];
            float4 a0 = *(const float4*)&Kj0[d4 * 4];
            float4 a1 = *(const float4*)&Kj1[d4 * 4];
            float4 a2 = *(const float4*)&Kj2[d4 * 4];
            float4 a3 = *(const float4*)&Kj3[d4 * 4];
            dkk0 += ki.x*a0.x + ki.y*a0.y + ki.z*a0.z + ki.w*a0.w;
            dkk1 += ki.x*a1.x + ki.y*a1.y + ki.z*a1.z + ki.w*a1.w;
            dkk2 += ki.x*a2.x + ki.y*a2.y + ki.z*a2.z + ki.w*a2.w;
            dkk3 += ki.x*a3.x + ki.y*a3.y + ki.z*a3.z + ki.w*a3.w;
            dqk0 += qi.x*a0.x + qi.y*a0.y + qi.z*a0.z + qi.w*a0.w;
            dqk1 += qi.x*a1.x + qi.y*a1.y + qi.z*a1.z + qi.w*a1.w;
            dqk2 += qi.x*a2.x + qi.y*a2.y + qi.z*a2.z + qi.w*a2.w;
            dqk3 += qi.x*a3.x + qi.y*a3.y + qi.z*a3.z + qi.w*a3.w;
        }
        float bi = BET[i];
        float* attg = g_att + ((size_t)(bh * NCH + ch)) * (CCH * CCH) + i * 32;
        int j;
        j = jq;      A[i*36+j] = (j <  i) ? bi*dkk0 : 0.f; attg[j] = (j <= i) ? dqk0 : 0.f;
        j = jq + 8;  A[i*36+j] = (j <  i) ? bi*dkk1 : 0.f; attg[j] = (j <= i) ? dqk1 : 0.f;
        j = jq + 16; A[i*36+j] = (j <  i) ? bi*dkk2 : 0.f; attg[j] = (j <= i) ? dqk2 : 0.f;
        j = jq + 24; A[i*36+j] = (j <  i) ? bi*dkk3 : 0.f; attg[j] = (j <= i) ? dqk3 : 0.f;
    }
    __syncthreads();

    // Forward substitution, register-resident per column (no barriers).
    {
        float rk[32], rv[32];
        float* ow = g_w + base + t;
        float* ou = g_u + base + t;
#pragma unroll
        for (int i = 0; i < 32; i++) {
            float accw = BET[i] * K[i * P1S + t];
            float accv = V[i * P1S + t];
            const int i4 = i >> 2;
#pragma unroll
            for (int b = 0; b < i4; b++) {
                float4 a = *(const float4*)&A[i * 36 + b * 4];
                accw -= a.x * rk[b*4+0] + a.y * rk[b*4+1]
                      + a.z * rk[b*4+2] + a.w * rk[b*4+3];
                accv -= a.x * rv[b*4+0] + a.y * rv[b*4+1]
                      + a.z * rv[b*4+2] + a.w * rv[b*4+3];
            }
#pragma unroll
            for (int j = i4 * 4; j < i; j++) {
                float a = A[i * 36 + j];
                accw -= a * rk[j];
                accv -= a * rv[j];
            }
            rk[i] = accw;
            rv[i] = accv;
            ow[(size_t)i * DKV] = accw;
            ou[(size_t)i * DKV] = accv;
        }
    }
}

// ============================================================================
// Phase 2s: the minimal sequential scan. Grid = (NJB, BHT) = 128 CTAs, 512 thr.
// Per chunk: WS = w@S ; UADJ = u - WS ; snapshot S + UADJ to global ;
// S += k^T @ UADJ.  Output computation moved to phase3.
// K tiles double-buffered (prefetched a full chunk ahead).
// ============================================================================
#define P2S 260

__global__ __launch_bounds__(512, 1)
void phase2s(float* __restrict__ out, int write_state)
{
    const int jb = blockIdx.x;
    const int bh = blockIdx.y;
    extern __shared__ float sm[];
    float* Wt   = sm;                          // 32 * 260
    float* Kt0  = Wt  + 32 * P2S;
    float* Kt1  = Kt0 + 32 * P2S;
    float* St   = Kt1 + 32 * P2S;              // 32 * 256 (S^T, swizzled)
    float* Usl0 = St  + 32 * 256;              // 32 * 36 each below
    float* Usl1 = Usl0 + 32 * 36;
    float* WSl  = Usl1 + 32 * 36;
    float* WSh  = WSl  + 32 * 36;
    float* UADJ = WSh  + 32 * 36;

    const int t = threadIdx.x;

    // zero S
#pragma unroll
    for (int r = 0; r < 16; r++) St[t + r * 512] = 0.f;

    // GEMM-A map: 2x2 (i,j) tile; halves split d; warp covers 4 ip x 8 jp
    const int half = t >> 8, tt = t & 255;
    const int w8 = tt >> 5, la = tt & 31;
    const int ip = (w8 >> 1) * 4 + (la >> 3);
    const int jp = (w8 & 1) * 8 + (la & 7);
    const int i0 = 2 * ip, i1 = i0 + 1;
    const int j0 = 2 * jp, j1 = j0 + 1;
    const int keyA = jp & 7;
    const int d4base = half << 5;
    // GEMM-C map
    const int jj = t & 31, dgh = t >> 5;       // dgh in [0,16)
    const int keyC = (jj >> 1) & 7;
    // UADJ map (512 threads, float2)
    const int ei = t >> 4, ej2 = (t & 15) * 2;
    // snapshot map: 16 floats/thread, row js, d4 block u16*4..+3
    const int js = t >> 4, u16 = t & 15;
    const int keyS = (js >> 1) & 7;

    const size_t bh_base = (size_t)bh * LSEQ * DKV;

    // ---- prime: W(0)->Wt, K(0)->Kt0, usl(0)->Usl0 ----
    {
        const float4* w4 = (const float4*)(g_w + bh_base);
        const float4* k4 = (const float4*)(g_kn + bh_base);
#pragma unroll
        for (int r = 0; r < 4; r++) {
            int f   = t + r * 512;
            int row = f >> 6, c4 = f & 63;
            cpa16(&Wt[row * P2S + c4 * 4], &w4[f]);
            cpa16(&Kt0[row * P2S + c4 * 4], &k4[f]);
        }
        if (t < 256) {
            int li = t >> 3, lj4 = (t & 7) * 4;
            cpa16(&Usl0[li * 36 + lj4], &g_u[bh_base + (size_t)li * DKV + jb * JBW + lj4]);
        }
        cpa_commit();
    }

    for (int ch = 0; ch < NCH; ch++) {
        const int pb = ch & 1;
        float* Ktc = pb ? Kt1 : Kt0;
        float* Ktn = pb ? Kt0 : Kt1;
        float* Usl = pb ? Usl1 : Usl0;
        float* UslN = pb ? Usl0 : Usl1;

        cpa_wait_all();
        __syncthreads();

        // prefetch K(ch+1) into the alternate buffer (full chunk of cover)
        if (ch + 1 < NCH) {
            const float4* k4 = (const float4*)(g_kn + bh_base + (size_t)(ch + 1) * CCH * DKV);
#pragma unroll
            for (int r = 0; r < 4; r++) {
                int f   = t + r * 512;
                int row = f >> 6, c4 = f & 63;
                cpa16(&Ktn[row * P2S + c4 * 4], &k4[f]);
            }
            cpa_commit();
        }

        // ---- GEMM A': WS = w @ S (f32x2, d-split halves) ----
        {
            unsigned long long w00 = 0, w01 = 0, w10 = 0, w11 = 0;
            const ulonglong2* wr0 = (const ulonglong2*)&Wt[i0 * P2S];
            const ulonglong2* wr1 = (const ulonglong2*)&Wt[i1 * P2S];
            const float* sr0 = &St[j0 * 256];
            const float* sr1 = &St[j1 * 256];
#pragma unroll 4
            for (int d4r = 0; d4r < 32; d4r++) {
                int d4 = d4base + d4r;
                int u  = d4 ^ keyA;
                ulonglong2 sv0 = *(const ulonglong2*)&sr0[u << 2];
                ulonglong2 sv1 = *(const ulonglong2*)&sr1[u << 2];
                ulonglong2 wv0 = wr0[d4];
                ulonglong2 wv1 = wr1[d4];
                w00 = ffma2(wv0.x, sv0.x, w00); w00 = ffma2(wv0.y, sv0.y, w00);
                w01 = ffma2(wv0.x, sv1.x, w01); w01 = ffma2(wv0.y, sv1.y, w01);
                w10 = ffma2(wv1.x, sv0.x, w10); w10 = ffma2(wv1.y, sv0.y, w10);
                w11 = ffma2(wv1.x, sv1.x, w11); w11 = ffma2(wv1.y, sv1.y, w11);
            }
            float* WSd = half ? WSh : WSl;
            WSd[i0 * 36 + j0] = fold2(w00);
            WSd[i0 * 36 + j1] = fold2(w01);
            WSd[i1 * 36 + j0] = fold2(w10);
            WSd[i1 * 36 + j1] = fold2(w11);
        }
        __syncthreads();

        const size_t slice = (size_t)((ch * BHT + bh) * NJB + jb);

        // ---- snapshot S_ch -> global ([j][d] layout, de-swizzled) ----
        {
            float* gS = g_S + slice * (DKV * JBW) + (size_t)js * DKV;
#pragma unroll
            for (int m = 0; m < 4; m++) {
                int d4 = u16 * 4 + m;
                float4 v = *(const float4*)&St[js * 256 + ((d4 ^ keyS) << 2)];
                *(float4*)&gS[d4 << 2] = v;
            }
        }

        // ---- GEMM-C S-row preload (St stable) ----
        ulonglong2 sa[4];
        {
            float* srow = &St[jj * 256];
#pragma unroll
            for (int m = 0; m < 4; m++) {
                int u = (dgh * 4 + m) ^ keyC;
                sa[m] = *(const ulonglong2*)&srow[u << 2];
            }
        }

        // ---- UADJ = u - WS_lo - WS_hi ; store to global ----
        {
            float2 uu = *(float2*)&Usl[ei * 36 + ej2];
            float2 wl = *(float2*)&WSl[ei * 36 + ej2];
            float2 wh = *(float2*)&WSh[ei * 36 + ej2];
            float2 r;
            r.x = uu.x - wl.x - wh.x;
            r.y = uu.y - wl.y - wh.y;
            *(float2*)&UADJ[ei * 36 + ej2] = r;
            *(float2*)&g_uadj[slice * (CCH * JBW) + ei * 32 + ej2] = r;
        }

        // prefetch W(ch+1), usl(ch+1) (Wt dead after GEMM-A barrier)
        if (ch + 1 < NCH) {
            const size_t nbase = bh_base + (size_t)(ch + 1) * CCH * DKV;
            const float4* w4 = (const float4*)(g_w + nbase);
#pragma unroll
            for (int r = 0; r < 4; r++) {
                int f   = t + r * 512;
                int row = f >> 6, c4 = f & 63;
                cpa16(&Wt[row * P2S + c4 * 4], &w4[f]);
            }
            if (t < 256) {
                int li = t >> 3, lj4 = (t & 7) * 4;
                cpa16(&UslN[li * 36 + lj4],
                      &g_u[nbase + (size_t)li * DKV + jb * JBW + lj4]);
            }
            cpa_commit();
        }
        __syncthreads();

        // ---- GEMM C: S += k^T @ UADJ ----
        {
            float* srow = &St[jj * 256];
#pragma unroll 4
            for (int i = 0; i < CCH; i++) {
                unsigned long long us = splat2(UADJ[i * 36 + jj]);
                const ulonglong2* kr = (const ulonglong2*)&Ktc[i * P2S + dgh * 16];
#pragma unroll
                for (int m = 0; m < 4; m++) {
                    ulonglong2 kv = kr[m];
                    sa[m].x = ffma2(kv.x, us, sa[m].x);
                    sa[m].y = ffma2(kv.y, us, sa[m].y);
                }
            }
#pragma unroll
            for (int m = 0; m < 4; m++) {
                int u = (dgh * 4 + m) ^ keyC;
                *(ulonglong2*)&srow[u << 2] = sa[m];
            }
        }
        __syncthreads();
    }

    // ---- final state S (second tuple element) ----
    if (write_state) {
        const size_t soff = OUT_ELEMS;
#pragma unroll 4
        for (int m = 0; m < 16; m++) {
            int d  = dgh * 16 + m;
            int u  = (dgh * 4 + (m >> 2)) ^ keyC;
            float val = St[jj * 256 + (u << 2) + (m & 3)];
            out[soff + ((size_t)bh * DKV + d) * DKV + jb * JBW + jj] = val;
        }
    }
}

// ============================================================================
// Phase 3: fully parallel output. Grid = (NCH, BHT) = 2048 CTAs, 256 threads,
// 2 CTAs/SM. Per jb slice: O = q @ S_ch + att @ uadj. S slices streamed via
// cp.async into the scan's swizzled layout; double-buffered.
// ============================================================================
__global__ __launch_bounds__(256, 2)
void phase3(float* __restrict__ out)
{
    const int ch = blockIdx.x;
    const int bh = blockIdx.y;
    extern __shared__ float sm[];
    float* Qt  = sm;                           // 32 * 260
    float* S0  = Qt + 32 * P2S;                // 32 * 256 swizzled
    float* S1  = S0 + 32 * 256;
    float* ATT = S1 + 32 * 256;                // 32 * 36
    float* UA0 = ATT + 32 * 36;
    float* UA1 = UA0 + 32 * 36;

    const int t = threadIdx.x;
    const int w8 = t >> 5, la = t & 31;
    const int ip = (w8 >> 1) * 4 + (la >> 3);
    const int jp = (w8 & 1) * 8 + (la & 7);
    const int i0 = 2 * ip, i1 = i0 + 1;
    const int j0 = 2 * jp, j1 = j0 + 1;
    const int keyA = jp & 7;

    const size_t base = ((size_t)bh * LSEQ + (size_t)ch * CCH) * DKV;
    const size_t slice0 = (size_t)((ch * BHT + bh) * NJB);

    // ---- prime: Q, att, S(0), uadj(0) ----
    {
        const float4* q4 = (const float4*)(g_qn + base);
#pragma unroll
        for (int r = 0; r < 8; r++) {
            int f   = t + r * 256;
            int row = f >> 6, c4 = f & 63;
            cpa16(&Qt[row * P2S + c4 * 4], &q4[f]);
        }
        {
            int li = t >> 3, lj4 = (t & 7) * 4;
            cpa16(&ATT[li * 36 + lj4],
                  &g_att[((size_t)(bh * NCH + ch)) * 1024 + li * 32 + lj4]);
            cpa16(&UA0[li * 36 + lj4],
                  &g_uadj[slice0 * (CCH * JBW) + li * 32 + lj4]);
        }
        // S slice 0: 2048 16B chunks / 256 threads = 8 each, swizzled dst
#pragma unroll
        for (int r = 0; r < 8; r++) {
            int c  = t + r * 256;
            int j  = c >> 6, d4 = c & 63;
            int u  = d4 ^ ((j >> 1) & 7);
            cpa16(&S0[j * 256 + (u << 2)],
                  &g_S[slice0 * (size_t)(DKV * JBW) + (size_t)j * DKV + (d4 << 2)]);
        }
        cpa_commit();
    }

    for (int jbl = 0; jbl < NJB; jbl++) {
        const int pb = jbl & 1;
        float* Sc = pb ? S1 : S0;
        float* Sn = pb ? S0 : S1;
        float* UAc = pb ? UA1 : UA0;
        float* UAn = pb ? UA0 : UA1;

        cpa_wait_all();
        __syncthreads();

        // prefetch next slice
        if (jbl + 1 < NJB) {
            const size_t sl = slice0 + (jbl + 1);
#pragma unroll
            for (int r = 0; r < 8; r++) {
                int c  = t + r * 256;
                int j  = c >> 6, d4 = c & 63;
                int u  = d4 ^ ((j >> 1) & 7);
                cpa16(&Sn[j * 256 + (u << 2)],
                      &g_S[sl * (size_t)(DKV * JBW) + (size_t)j * DKV + (d4 << 2)]);
            }
            {
                int li = t >> 3, lj4 = (t & 7) * 4;
                cpa16(&UAn[li * 36 + lj4],
                      &g_uadj[sl * (CCH * JBW) + li * 32 + lj4]);
            }
            cpa_commit();
        }

        // ---- O = q @ S (full d=256) ----
        unsigned long long p00 = 0, p01 = 0, p10 = 0, p11 = 0;
        {
            const ulonglong2* qr0 = (const ulonglong2*)&Qt[i0 * P2S];
            const ulonglong2* qr1 = (const ulonglong2*)&Qt[i1 * P2S];
            const float* sr0 = &Sc[j0 * 256];
            const float* sr1 = &Sc[j1 * 256];
#pragma unroll 4
            for (int d4 = 0; d4 < 64; d4++) {
                int u = d4 ^ keyA;
                ulonglong2 sv0 = *(const ulonglong2*)&sr0[u << 2];
                ulonglong2 sv1 = *(const ulonglong2*)&sr1[u << 2];
                ulonglong2 qv0 = qr0[d4];
                ulonglong2 qv1 = qr1[d4];
                p00 = ffma2(qv0.x, sv0.x, p00); p00 = ffma2(qv0.y, sv0.y, p00);
                p01 = ffma2(qv0.x, sv1.x, p01); p01 = ffma2(qv0.y, sv1.y, p01);
                p10 = ffma2(qv1.x, sv0.x, p10); p10 = ffma2(qv1.y, sv0.y, p10);
                p11 = ffma2(qv1.x, sv1.x, p11); p11 = ffma2(qv1.y, sv1.y, p11);
            }
        }
        float o00 = fold2(p00), o01 = fold2(p01);
        float o10 = fold2(p10), o11 = fold2(p11);

        // ---- += att @ uadj ----
        {
            const float* ar0 = &ATT[i0 * 36];
            const float* ar1 = &ATT[i1 * 36];
#pragma unroll 8
            for (int ii = 0; ii < CCH; ii++) {
                float a0 = ar0[ii];
                float a1 = ar1[ii];
                float2 ub = *(const float2*)&UAc[ii * 36 + j0];
                o00 += a0 * ub.x; o01 += a0 * ub.y;
                o10 += a1 * ub.x; o11 += a1 * ub.y;
            }
        }

        // ---- store O block ----
        {
            float2 r0; r0.x = o00; r0.y = o01;
            float2 r1; r1.x = o10; r1.y = o11;
            *(float2*)&out[base + (size_t)i0 * DKV + jbl * JBW + j0] = r0;
            *(float2*)&out[base + (size_t)i1 * DKV + jbl * JBW + j0] = r1;
        }
    }
}

// ============================================================================

#define SM1_BYTES ((32 * P1S * 3 + 32 * 36 + 512 + 32 + 64) * sizeof(float))
#define SM2_BYTES ((32 * P2S * 3 + 32 * 256 + 5 * 32 * 36) * sizeof(float))
#define SM3_BYTES ((32 * P2S + 2 * 32 * 256 + 3 * 32 * 36) * sizeof(float))

extern "C" void kernel_launch(void* const* d_in, const int* in_sizes, int n_in,
                              void* d_out, int out_size)
{
    const float* q    = (const float*)d_in[0];
    const float* k    = (const float*)d_in[1];
    const float* v    = (const float*)d_in[2];
    const float* beta = (const float*)d_in[3];
    float* out = (float*)d_out;

    cudaFuncSetAttribute(phase1,  cudaFuncAttributeMaxDynamicSharedMemorySize, SM1_BYTES);
    cudaFuncSetAttribute(phase2s, cudaFuncAttributeMaxDynamicSharedMemorySize, SM2_BYTES);
    cudaFuncSetAttribute(phase3,  cudaFuncAttributeMaxDynamicSharedMemorySize, SM3_BYTES);

    phase1<<<dim3(NCH, BHT), 256, SM1_BYTES>>>(q, k, v, beta);

    int ws = ((size_t)out_size >= OUT_ELEMS + STATE_ELEMS) ? 1 : 0;
    phase2s<<<dim3(NJB, BHT), 512, SM2_BYTES>>>(out, ws);

    phase3<<<dim3(NCH, BHT), 256, SM3_BYTES>>>(out);
}

// round 14
// speedup vs baseline: 1.2956x; 1.2956x over previous
#include <cuda_runtime.h>

// DeltaNet chunkwise delta rule.
// Shapes fixed by the problem: b=4, h=4, L=4096, dk=dv=256, chunk=32.

#define LSEQ  4096
#define DKV   256
#define CCH   32
#define NCH   (LSEQ / CCH)      // 128 chunks
#define BHT   16                // b*h
#define JBW   32                // dv block width in phase 2
#define NJB   (DKV / JBW)       // 8 column blocks

#define OUT_ELEMS   ((size_t)BHT * LSEQ * DKV)        // 16777216
#define STATE_ELEMS ((size_t)BHT * DKV * DKV)         // 1048576

// Scratch (device globals; no allocation allowed)
__device__ float g_qn [(size_t)BHT * LSEQ * DKV];
__device__ float g_kn [(size_t)BHT * LSEQ * DKV];
__device__ float g_w  [(size_t)BHT * LSEQ * DKV];
__device__ float g_u  [(size_t)BHT * LSEQ * DKV];
__device__ float g_att[(size_t)BHT * NCH * CCH * CCH];

// ---- packed f32x2 helpers (2x FFMA throughput vs 3-reg FFMA on sm_103a) ----
__device__ __forceinline__ unsigned long long ffma2(unsigned long long a,
                                                    unsigned long long b,
                                                    unsigned long long c) {
    unsigned long long d;
    asm("fma.rn.f32x2 %0, %1, %2, %3;" : "=l"(d) : "l"(a), "l"(b), "l"(c));
    return d;
}
__device__ __forceinline__ unsigned long long splat2(float x) {
    unsigned long long d;
    unsigned int r = __float_as_uint(x);
    asm("mov.b64 %0, {%1, %1};" : "=l"(d) : "r"(r));
    return d;
}
__device__ __forceinline__ float fold2(unsigned long long a) {
    unsigned int lo, hi;
    asm("mov.b64 {%0, %1}, %2;" : "=r"(lo), "=r"(hi) : "l"(a));
    return __uint_as_float(lo) + __uint_as_float(hi);
}

// ---- cp.async: global -> shared 16B, no register round-trip ----
__device__ __forceinline__ void cpa16(void* smem_dst, const void* gmem_src) {
    unsigned int s = (unsigned int)__cvta_generic_to_shared(smem_dst);
    asm volatile("cp.async.ca.shared.global [%0], [%1], 16;" :: "r"(s), "l"(gmem_src));
}
__device__ __forceinline__ void cpa_commit() {
    asm volatile("cp.async.commit_group;");
}
__device__ __forceinline__ void cpa_wait_all() {
    asm volatile("cp.async.wait_group 0;" ::: "memory");
}

// ============================================================================
// Phase 1: per-chunk preprocessing (parallel over bh * chunks = 2048 CTAs).
// ============================================================================
#define P1S 260

__global__ __launch_bounds__(256, 2)
void phase1(const float* __restrict__ q, const float* __restrict__ k,
            const float* __restrict__ v, const float* __restrict__ beta)
{
    const int ch = blockIdx.x;
    const int bh = blockIdx.y;
    extern __shared__ float sm[];
    float* Q   = sm;                         // 32 * 260
    float* K   = Q + 32 * P1S;
    float* V   = K + 32 * P1S;
    float* A   = V + 32 * P1S;               // 32 * 36
    float* RED = A + 32 * 36;                // 512
    float* BET = RED + 512;                  // 32
    float* NRM = BET + 32;                   // 64

    const int t = threadIdx.x;
    const size_t base = ((size_t)bh * LSEQ + (size_t)ch * CCH) * DKV;
    const float4* q4 = (const float4*)(q + base);
    const float4* k4 = (const float4*)(k + base);
    const float4* v4 = (const float4*)(v + base);

#pragma unroll
    for (int r = 0; r < 8; r++) {
        int f   = t + r * 256;
        int row = f >> 6, c4 = f & 63;
        cpa16(&Q[row * P1S + c4 * 4], &q4[f]);
        cpa16(&K[row * P1S + c4 * 4], &k4[f]);
        cpa16(&V[row * P1S + c4 * 4], &v4[f]);
    }
    if (t < CCH) BET[t] = beta[(size_t)bh * LSEQ + ch * CCH + t];
    cpa_commit();
    cpa_wait_all();
    __syncthreads();

    // row sum-of-squares for q and k
    {
        int r = t >> 3, s = t & 7;
        float aq = 0.f, ak = 0.f;
#pragma unroll
        for (int m = 0; m < 32; m++) {
            float xq = Q[r * P1S + s * 32 + m];
            float xk = K[r * P1S + s * 32 + m];
            aq += xq * xq;
            ak += xk * xk;
        }
        RED[r * 8 + s]       = aq;
        RED[256 + r * 8 + s] = ak;
    }
    __syncthreads();
    if (t < 64) {
        int r = t & 31, wsel = t >> 5;
        float ssum = 0.f;
#pragma unroll
        for (int s = 0; s < 8; s++) ssum += RED[wsel * 256 + r * 8 + s];
        NRM[t] = rsqrtf(ssum);
    }
    __syncthreads();

    // normalize q,k (write qn,kn straight to global) ; v *= beta
    {
        float4* oq = (float4*)(g_qn + base);
        float4* ok = (float4*)(g_kn + base);
#pragma unroll
        for (int r = 0; r < 8; r++) {
            int f   = t + r * 256;
            int row = f >> 6, c4 = f & 63;
            float nq = NRM[row], nk = NRM[32 + row], be = BET[row];
            float4 xq = *(float4*)&Q[row * P1S + c4 * 4];
            xq.x *= nq; xq.y *= nq; xq.z *= nq; xq.w *= nq;
            *(float4*)&Q[row * P1S + c4 * 4] = xq;
            oq[f] = xq;
            float4 xk = *(float4*)&K[row * P1S + c4 * 4];
            xk.x *= nk; xk.y *= nk; xk.z *= nk; xk.w *= nk;
            *(float4*)&K[row * P1S + c4 * 4] = xk;
            ok[f] = xk;
            float4 xv = *(float4*)&V[row * P1S + c4 * 4];
            xv.x *= be; xv.y *= be; xv.z *= be; xv.w *= be;
            *(float4*)&V[row * P1S + c4 * 4] = xv;
        }
    }
    __syncthreads();

    // A (strict lower, beta_i * kn_i . kn_j) and att (tril incl diag).
    {
        const int w8 = t >> 5, la = t & 31;
        const int i  = w8 * 4 + (la >> 3);
        const int jq = la & 7;
        float dkk0 = 0.f, dkk1 = 0.f, dkk2 = 0.f, dkk3 = 0.f;
        float dqk0 = 0.f, dqk1 = 0.f, dqk2 = 0.f, dqk3 = 0.f;
        const float* Ki = &K[i * P1S];
        const float* Qi = &Q[i * P1S];
        const float* Kj0 = &K[(jq     ) * P1S];
        const float* Kj1 = &K[(jq +  8) * P1S];
        const float* Kj2 = &K[(jq + 16) * P1S];
        const float* Kj3 = &K[(jq + 24) * P1S];
#pragma unroll 8
        for (int d4 = 0; d4 < 64; d4++) {
            float4 ki = *(const float4*)&Ki[d4 * 4];
            float4 qi = *(const float4*)&Qi[d4 * 4];
            float4 a0 = *(const float4*)&Kj0[d4 * 4];
            float4 a1 = *(const float4*)&Kj1[d4 * 4];
            float4 a2 = *(const float4*)&Kj2[d4 * 4];
            float4 a3 = *(const float4*)&Kj3[d4 * 4];
            dkk0 += ki.x*a0.x + ki.y*a0.y + ki.z*a0.z + ki.w*a0.w;
            dkk1 += ki.x*a1.x + ki.y*a1.y + ki.z*a1.z + ki.w*a1.w;
            dkk2 += ki.x*a2.x + ki.y*a2.y + ki.z*a2.z + ki.w*a2.w;
            dkk3 += ki.x*a3.x + ki.y*a3.y + ki.z*a3.z + ki.w*a3.w;
            dqk0 += qi.x*a0.x + qi.y*a0.y + qi.z*a0.z + qi.w*a0.w;
            dqk1 += qi.x*a1.x + qi.y*a1.y + qi.z*a1.z + qi.w*a1.w;
            dqk2 += qi.x*a2.x + qi.y*a2.y + qi.z*a2.z + qi.w*a2.w;
            dqk3 += qi.x*a3.x + qi.y*a3.y + qi.z*a3.z + qi.w*a3.w;
        }
        float bi = BET[i];
        float* attg = g_att + ((size_t)(bh * NCH + ch)) * (CCH * CCH) + i * 32;
        int j;
        j = jq;      A[i*36+j] = (j <  i) ? bi*dkk0 : 0.f; attg[j] = (j <= i) ? dqk0 : 0.f;
        j = jq + 8;  A[i*36+j] = (j <  i) ? bi*dkk1 : 0.f; attg[j] = (j <= i) ? dqk1 : 0.f;
        j = jq + 16; A[i*36+j] = (j <  i) ? bi*dkk2 : 0.f; attg[j] = (j <= i) ? dqk2 : 0.f;
        j = jq + 24; A[i*36+j] = (j <  i) ? bi*dkk3 : 0.f; attg[j] = (j <= i) ? dqk3 : 0.f;
    }
    __syncthreads();

    // Forward substitution, register-resident per column (no barriers).
    {
        float rk[32], rv[32];
        float* ow = g_w + base + t;
        float* ou = g_u + base + t;
#pragma unroll
        for (int i = 0; i < 32; i++) {
            float accw = BET[i] * K[i * P1S + t];
            float accv = V[i * P1S + t];
            const int i4 = i >> 2;
#pragma unroll
            for (int b = 0; b < i4; b++) {
                float4 a = *(const float4*)&A[i * 36 + b * 4];
                accw -= a.x * rk[b*4+0] + a.y * rk[b*4+1]
                      + a.z * rk[b*4+2] + a.w * rk[b*4+3];
                accv -= a.x * rv[b*4+0] + a.y * rv[b*4+1]
                      + a.z * rv[b*4+2] + a.w * rv[b*4+3];
            }
#pragma unroll
            for (int j = i4 * 4; j < i; j++) {
                float a = A[i * 36 + j];
                accw -= a * rk[j];
                accv -= a * rv[j];
            }
            rk[i] = accw;
            rv[i] = accv;
            ow[(size_t)i * DKV] = accw;
            ou[(size_t)i * DKV] = accv;
        }
    }
}

// ============================================================================
// Phase 2: sequential scan over chunks. Grid = (NJB, BHT) = 128 CTAs, 512 thr.
// GEMM-A: 2x4 register tile, 4-way d split (4 products per LDS.128 — 33%
// fewer smem wavefronts than 2x2/2-way). S swizzle key = (j>>2)&7 so the
// 4-consecutive-j loads stay single-wavefront per warp.
// Software-pipelined loads as in R12.
// ============================================================================
#define P2S 260

__global__ __launch_bounds__(512, 1)
void phase2(float* __restrict__ out, int write_state)
{
    const int jb = blockIdx.x;
    const int bh = blockIdx.y;
    extern __shared__ float sm[];
    float* Wt   = sm;                          // 32 * 260
    float* Qt   = Wt + 32 * P2S;
    float* Kt   = Qt + 32 * P2S;
    float* St   = Kt + 32 * P2S;               // 32 * 256 (S^T, swizzled key=(j>>2)&7)
    float* Usl0 = St + 32 * 256;               // 32 * 36 each below
    float* Usl1 = Usl0 + 32 * 36;
    float* ATT0 = Usl1 + 32 * 36;
    float* ATT1 = ATT0 + 32 * 36;
    float* WSp  = ATT1 + 32 * 36;              // 4 partial buffers (d-slices)
    float* QSp  = WSp  + 4 * 32 * 36;          // 4 partial buffers
    float* UADJ = QSp  + 4 * 32 * 36;

    const int t = threadIdx.x;

    // zero S
#pragma unroll
    for (int r = 0; r < 16; r++) St[t + r * 512] = 0.f;

    // GEMM-A map: 2x4 (i,j) tile; 4 d-slices; warp covers 4 ip x 8 jq
    const int quarter = t >> 7;                // d-slice 0..3
    const int r128 = t & 127;
    const int w4 = r128 >> 5, la = r128 & 31;
    const int ip = (w4 << 2) | (la >> 3);      // 0..15
    const int jq = la & 7;                     // 0..7 (j0 = 4*jq, 4 consecutive)
    const int i0 = 2 * ip, i1 = i0 + 1;
    const int j0 = 4 * jq;
    const int d4base = quarter << 4;           // 16 d4-steps per slice
    float* WSq = WSp + quarter * (32 * 36);
    float* QSq = QSp + quarter * (32 * 36);
    // GEMM-C map: thread owns (row jj of S^T, 16-wide d block dgh)
    const int jj = t & 31, dgh = t >> 5;       // dgh in [0,16)
    const int keyC = (jj >> 2) & 7;
    // epilogue/merge map (512 threads, float2)
    const int ei = t >> 4, ej2 = (t & 15) * 2;

    const size_t bh_base  = (size_t)bh * LSEQ * DKV;
    const size_t att_base = (size_t)(bh * NCH) * 1024;

    // ---- prime pipeline: load chunk 0 tiles ----
    {
        const size_t base = bh_base;   // ch = 0
        const float4* w4p = (const float4*)(g_w + base);
        const float4* q4p = (const float4*)(g_qn + base);
        const float4* k4p = (const float4*)(g_kn + base);
#pragma unroll
        for (int r = 0; r < 4; r++) {
            int f   = t + r * 512;
            int row = f >> 6, c4 = f & 63;
            cpa16(&Wt[row * P2S + c4 * 4], &w4p[f]);
            cpa16(&Qt[row * P2S + c4 * 4], &q4p[f]);
            cpa16(&Kt[row * P2S + c4 * 4], &k4p[f]);
        }
        if (t < 256) {
            int li = t >> 3, lj4 = (t & 7) * 4;
            cpa16(&Usl0[li * 36 + lj4], &g_u[base + (size_t)li * DKV + jb * JBW + lj4]);
            cpa16(&ATT0[li * 36 + lj4], &g_att[att_base + li * 32 + lj4]);
        }
        cpa_commit();
    }

    for (int ch = 0; ch < NCH; ch++) {
        const int p = ch & 1;
        float* Usl  = p ? Usl1 : Usl0;
        float* ATTs = p ? ATT1 : ATT0;
        float* UslN = p ? Usl0 : Usl1;
        float* ATTN = p ? ATT0 : ATT1;

        cpa_wait_all();
        __syncthreads();

        // ---- GEMM A: WS = w @ S, QS = q @ S  (f32x2, 2x4 tile, 4 d-slices) ----
        {
            unsigned long long wa[2][4], qa[2][4];
#pragma unroll
            for (int a = 0; a < 2; a++)
#pragma unroll
                for (int b = 0; b < 4; b++) { wa[a][b] = 0; qa[a][b] = 0; }

            const ulonglong2* wr0 = (const ulonglong2*)&Wt[i0 * P2S];
            const ulonglong2* wr1 = (const ulonglong2*)&Wt[i1 * P2S];
            const ulonglong2* qr0 = (const ulonglong2*)&Qt[i0 * P2S];
            const ulonglong2* qr1 = (const ulonglong2*)&Qt[i1 * P2S];
            const float* sr0 = &St[(j0 + 0) * 256];
            const float* sr1 = &St[(j0 + 1) * 256];
            const float* sr2 = &St[(j0 + 2) * 256];
            const float* sr3 = &St[(j0 + 3) * 256];
#pragma unroll 2
            for (int d4r = 0; d4r < 16; d4r++) {
                int d4 = d4base + d4r;
                int u  = (d4 ^ jq) << 2;
                ulonglong2 wv0 = wr0[d4];
                ulonglong2 wv1 = wr1[d4];
                ulonglong2 qv0 = qr0[d4];
                ulonglong2 qv1 = qr1[d4];
                ulonglong2 sv0 = *(const ulonglong2*)&sr0[u];
                ulonglong2 sv1 = *(const ulonglong2*)&sr1[u];
                ulonglong2 sv2 = *(const ulonglong2*)&sr2[u];
                ulonglong2 sv3 = *(const ulonglong2*)&sr3[u];
                wa[0][0] = ffma2(wv0.x, sv0.x, wa[0][0]); wa[0][0] = ffma2(wv0.y, sv0.y, wa[0][0]);
                wa[0][1] = ffma2(wv0.x, sv1.x, wa[0][1]); wa[0][1] = ffma2(wv0.y, sv1.y, wa[0][1]);
                wa[0][2] = ffma2(wv0.x, sv2.x, wa[0][2]); wa[0][2] = ffma2(wv0.y, sv2.y, wa[0][2]);
                wa[0][3] = ffma2(wv0.x, sv3.x, wa[0][3]); wa[0][3] = ffma2(wv0.y, sv3.y, wa[0][3]);
                wa[1][0] = ffma2(wv1.x, sv0.x, wa[1][0]); wa[1][0] = ffma2(wv1.y, sv0.y, wa[1][0]);
                wa[1][1] = ffma2(wv1.x, sv1.x, wa[1][1]); wa[1][1] = ffma2(wv1.y, sv1.y, wa[1][1]);
                wa[1][2] = ffma2(wv1.x, sv2.x, wa[1][2]); wa[1][2] = ffma2(wv1.y, sv2.y, wa[1][2]);
                wa[1][3] = ffma2(wv1.x, sv3.x, wa[1][3]); wa[1][3] = ffma2(wv1.y, sv3.y, wa[1][3]);
                qa[0][0] = ffma2(qv0.x, sv0.x, qa[0][0]); qa[0][0] = ffma2(qv0.y, sv0.y, qa[0][0]);
                qa[0][1] = ffma2(qv0.x, sv1.x, qa[0][1]); qa[0][1] = ffma2(qv0.y, sv1.y, qa[0][1]);
                qa[0][2] = ffma2(qv0.x, sv2.x, qa[0][2]); qa[0][2] = ffma2(qv0.y, sv2.y, qa[0][2]);
                qa[0][3] = ffma2(qv0.x, sv3.x, qa[0][3]); qa[0][3] = ffma2(qv0.y, sv3.y, qa[0][3]);
                qa[1][0] = ffma2(qv1.x, sv0.x, qa[1][0]); qa[1][0] = ffma2(qv1.y, sv0.y, qa[1][0]);
                qa[1][1] = ffma2(qv1.x, sv1.x, qa[1][1]); qa[1][1] = ffma2(qv1.y, sv1.y, qa[1][1]);
                qa[1][2] = ffma2(qv1.x, sv2.x, qa[1][2]); qa[1][2] = ffma2(qv1.y, sv2.y, qa[1][2]);
                qa[1][3] = ffma2(qv1.x, sv3.x, qa[1][3]); qa[1][3] = ffma2(qv1.y, sv3.y, qa[1][3]);
            }
            float4 f;
            f.x = fold2(wa[0][0]); f.y = fold2(wa[0][1]);
            f.z = fold2(wa[0][2]); f.w = fold2(wa[0][3]);
            *(float4*)&WSq[i0 * 36 + j0] = f;
            f.x = fold2(wa[1][0]); f.y = fold2(wa[1][1]);
            f.z = fold2(wa[1][2]); f.w = fold2(wa[1][3]);
            *(float4*)&WSq[i1 * 36 + j0] = f;
            f.x = fold2(qa[0][0]); f.y = fold2(qa[0][1]);
            f.z = fold2(qa[0][2]); f.w = fold2(qa[0][3]);
            *(float4*)&QSq[i0 * 36 + j0] = f;
            f.x = fold2(qa[1][0]); f.y = fold2(qa[1][1]);
            f.z = fold2(qa[1][2]); f.w = fold2(qa[1][3]);
            *(float4*)&QSq[i1 * 36 + j0] = f;
        }
        __syncthreads();

        // ---- GEMM-C S-row preload (St stable now) overlapping UADJ pass ----
        ulonglong2 sa[4];
        {
            float* srow = &St[jj * 256];
#pragma unroll
            for (int m = 0; m < 4; m++) {
                int u = (dgh * 4 + m) ^ keyC;
                sa[m] = *(const ulonglong2*)&srow[u << 2];
            }
        }

        // ---- UADJ = u - sum of 4 WS partials (512 threads, float2) ----
        {
            float2 uu = *(float2*)&Usl[ei * 36 + ej2];
            float2 w0 = *(float2*)&WSp[0 * 32 * 36 + ei * 36 + ej2];
            float2 w1 = *(float2*)&WSp[1 * 32 * 36 + ei * 36 + ej2];
            float2 w2 = *(float2*)&WSp[2 * 32 * 36 + ei * 36 + ej2];
            float2 w3 = *(float2*)&WSp[3 * 32 * 36 + ei * 36 + ej2];
            float2 r;
            r.x = uu.x - w0.x - w1.x - w2.x - w3.x;
            r.y = uu.y - w0.y - w1.y - w2.y - w3.y;
            *(float2*)&UADJ[ei * 36 + ej2] = r;
        }
        __syncthreads();

        // ---- prefetch next chunk's W/Q tiles + usl/att (Wt/Qt now dead) ----
        if (ch + 1 < NCH) {
            const size_t nbase = bh_base + (size_t)(ch + 1) * CCH * DKV;
            const float4* w4p = (const float4*)(g_w + nbase);
            const float4* q4p = (const float4*)(g_qn + nbase);
#pragma unroll
            for (int r = 0; r < 4; r++) {
                int f   = t + r * 512;
                int row = f >> 6, c4 = f & 63;
                cpa16(&Wt[row * P2S + c4 * 4], &w4p[f]);
                cpa16(&Qt[row * P2S + c4 * 4], &q4p[f]);
            }
            if (t < 256) {
                int li = t >> 3, lj4 = (t & 7) * 4;
                cpa16(&UslN[li * 36 + lj4],
                      &g_u[nbase + (size_t)li * DKV + jb * JBW + lj4]);
                cpa16(&ATTN[li * 36 + lj4],
                      &g_att[att_base + (size_t)(ch + 1) * 1024 + li * 32 + lj4]);
            }
            cpa_commit();
        }

        // ---- GEMM C: S += k^T @ UADJ  (register-resident RMW) ----
        {
            float* srow = &St[jj * 256];
#pragma unroll 4
            for (int i = 0; i < CCH; i++) {
                unsigned long long us = splat2(UADJ[i * 36 + jj]);
                const ulonglong2* kr = (const ulonglong2*)&Kt[i * P2S + dgh * 16];
#pragma unroll
                for (int m = 0; m < 4; m++) {
                    ulonglong2 kv = kr[m];
                    sa[m].x = ffma2(kv.x, us, sa[m].x);
                    sa[m].y = ffma2(kv.y, us, sa[m].y);
                }
            }
#pragma unroll
            for (int m = 0; m < 4; m++) {
                int u = (dgh * 4 + m) ^ keyC;
                *(ulonglong2*)&srow[u << 2] = sa[m];
            }
        }
        __syncthreads();

        // ---- prefetch next chunk's K tile (Kt now dead) ----
        if (ch + 1 < NCH) {
            const size_t nbase = bh_base + (size_t)(ch + 1) * CCH * DKV;
            const float4* k4p = (const float4*)(g_kn + nbase);
#pragma unroll
            for (int r = 0; r < 4; r++) {
                int f   = t + r * 512;
                int row = f >> 6, c4 = f & 63;
                cpa16(&Kt[row * P2S + c4 * 4], &k4p[f]);
            }
            cpa_commit();
        }

        // ---- O = sum QS + att @ UADJ ; write to global (512 threads, float2) ----
        {
            float2 q0 = *(float2*)&QSp[0 * 32 * 36 + ei * 36 + ej2];
            float2 q1 = *(float2*)&QSp[1 * 32 * 36 + ei * 36 + ej2];
            float2 q2 = *(float2*)&QSp[2 * 32 * 36 + ei * 36 + ej2];
            float2 q3 = *(float2*)&QSp[3 * 32 * 36 + ei * 36 + ej2];
            float2 o;
            o.x = (q0.x + q1.x) + (q2.x + q3.x);
            o.y = (q0.y + q1.y) + (q2.y + q3.y);
#pragma unroll 8
            for (int ii = 0; ii < CCH; ii++) {
                float a = ATTs[ei * 36 + ii];   // zero above diag
                float2 ub = *(float2*)&UADJ[ii * 36 + ej2];
                o.x += a * ub.x;
                o.y += a * ub.y;
            }
            *(float2*)&out[((size_t)bh * LSEQ + (size_t)ch * CCH + ei) * DKV +
                           jb * JBW + ej2] = o;
        }
        // no trailing barrier: loop-top wait + __syncthreads orders everything
    }

    // ---- final state S (second tuple element) ----
    if (write_state) {
        __syncthreads();
        const size_t soff = OUT_ELEMS;
#pragma unroll 4
        for (int m = 0; m < 16; m++) {
            int d  = dgh * 16 + m;
            int u  = (dgh * 4 + (m >> 2)) ^ keyC;
            float val = St[jj * 256 + (u << 2) + (m & 3)];
            out[soff + ((size_t)bh * DKV + d) * DKV + jb * JBW + jj] = val;
        }
    }
}

// ============================================================================

#define SM1_BYTES ((32 * P1S * 3 + 32 * 36 + 512 + 32 + 64) * sizeof(float))
#define SM2_BYTES ((32 * P2S * 3 + 32 * 256 + 13 * 32 * 36) * sizeof(float))

extern "C" void kernel_launch(void* const* d_in, const int* in_sizes, int n_in,
                              void* d_out, int out_size)
{
    const float* q    = (const float*)d_in[0];
    const float* k    = (const float*)d_in[1];
    const float* v    = (const float*)d_in[2];
    const float* beta = (const float*)d_in[3];
    float* out = (float*)d_out;

    cudaFuncSetAttribute(phase1, cudaFuncAttributeMaxDynamicSharedMemorySize, SM1_BYTES);
    cudaFuncSetAttribute(phase2, cudaFuncAttributeMaxDynamicSharedMemorySize, SM2_BYTES);

    phase1<<<dim3(NCH, BHT), 256, SM1_BYTES>>>(q, k, v, beta);

    int ws = ((size_t)out_size >= OUT_ELEMS + STATE_ELEMS) ? 1 : 0;
    phase2<<<dim3(NJB, BHT), 512, SM2_BYTES>>>(out, ws);
}

// round 15
// speedup vs baseline: 1.5010x; 1.1585x over previous
#include <cuda_runtime.h>

// DeltaNet chunkwise delta rule.
// Shapes fixed by the problem: b=4, h=4, L=4096, dk=dv=256, chunk=32.

#define LSEQ  4096
#define DKV   256
#define CCH   32
#define NCH   (LSEQ / CCH)      // 128 chunks
#define BHT   16                // b*h
#define JBW   32                // dv block width in phase 2
#define NJB   (DKV / JBW)       // 8 column blocks

#define OUT_ELEMS   ((size_t)BHT * LSEQ * DKV)        // 16777216
#define STATE_ELEMS ((size_t)BHT * DKV * DKV)         // 1048576

// Scratch (device globals; no allocation allowed)
__device__ float g_qn [(size_t)BHT * LSEQ * DKV];
__device__ float g_kn [(size_t)BHT * LSEQ * DKV];
__device__ float g_w  [(size_t)BHT * LSEQ * DKV];
__device__ float g_u  [(size_t)BHT * LSEQ * DKV];
__device__ float g_att[(size_t)BHT * NCH * CCH * CCH];

// ---- packed f32x2 helpers (2x FFMA throughput vs 3-reg FFMA on sm_103a) ----
__device__ __forceinline__ unsigned long long ffma2(unsigned long long a,
                                                    unsigned long long b,
                                                    unsigned long long c) {
    unsigned long long d;
    asm("fma.rn.f32x2 %0, %1, %2, %3;" : "=l"(d) : "l"(a), "l"(b), "l"(c));
    return d;
}
__device__ __forceinline__ unsigned long long splat2(float x) {
    unsigned long long d;
    unsigned int r = __float_as_uint(x);
    asm("mov.b64 %0, {%1, %1};" : "=l"(d) : "r"(r));
    return d;
}
__device__ __forceinline__ float fold2(unsigned long long a) {
    unsigned int lo, hi;
    asm("mov.b64 {%0, %1}, %2;" : "=r"(lo), "=r"(hi) : "l"(a));
    return __uint_as_float(lo) + __uint_as_float(hi);
}

// ---- cp.async: global -> shared 16B, no register round-trip ----
__device__ __forceinline__ void cpa16(void* smem_dst, const void* gmem_src) {
    unsigned int s = (unsigned int)__cvta_generic_to_shared(smem_dst);
    asm volatile("cp.async.ca.shared.global [%0], [%1], 16;" :: "r"(s), "l"(gmem_src));
}
__device__ __forceinline__ void cpa_commit() {
    asm volatile("cp.async.commit_group;");
}
__device__ __forceinline__ void cpa_wait_all() {
    asm volatile("cp.async.wait_group 0;" ::: "memory");
}

// ============================================================================
// Phase 1: per-chunk preprocessing (parallel over bh * chunks = 2048 CTAs).
// ============================================================================
#define P1S 260

__global__ __launch_bounds__(256, 2)
void phase1(const float* __restrict__ q, const float* __restrict__ k,
            const float* __restrict__ v, const float* __restrict__ beta)
{
    const int ch = blockIdx.x;
    const int bh = blockIdx.y;
    extern __shared__ float sm[];
    float* Q   = sm;                         // 32 * 260
    float* K   = Q + 32 * P1S;
    float* V   = K + 32 * P1S;
    float* A   = V + 32 * P1S;               // 32 * 36
    float* RED = A + 32 * 36;                // 512
    float* BET = RED + 512;                  // 32
    float* NRM = BET + 32;                   // 64

    const int t = threadIdx.x;
    const size_t base = ((size_t)bh * LSEQ + (size_t)ch * CCH) * DKV;
    const float4* q4 = (const float4*)(q + base);
    const float4* k4 = (const float4*)(k + base);
    const float4* v4 = (const float4*)(v + base);

#pragma unroll
    for (int r = 0; r < 8; r++) {
        int f   = t + r * 256;
        int row = f >> 6, c4 = f & 63;
        cpa16(&Q[row * P1S + c4 * 4], &q4[f]);
        cpa16(&K[row * P1S + c4 * 4], &k4[f]);
        cpa16(&V[row * P1S + c4 * 4], &v4[f]);
    }
    if (t < CCH) BET[t] = beta[(size_t)bh * LSEQ + ch * CCH + t];
    cpa_commit();
    cpa_wait_all();
    __syncthreads();

    // row sum-of-squares for q and k
    {
        int r = t >> 3, s = t & 7;
        float aq = 0.f, ak = 0.f;
#pragma unroll
        for (int m = 0; m < 32; m++) {
            float xq = Q[r * P1S + s * 32 + m];
            float xk = K[r * P1S + s * 32 + m];
            aq += xq * xq;
            ak += xk * xk;
        }
        RED[r * 8 + s]       = aq;
        RED[256 + r * 8 + s] = ak;
    }
    __syncthreads();
    if (t < 64) {
        int r = t & 31, wsel = t >> 5;
        float ssum = 0.f;
#pragma unroll
        for (int s = 0; s < 8; s++) ssum += RED[wsel * 256 + r * 8 + s];
        NRM[t] = rsqrtf(ssum);
    }
    __syncthreads();

    // normalize q,k (write qn,kn straight to global) ; v *= beta
    {
        float4* oq = (float4*)(g_qn + base);
        float4* ok = (float4*)(g_kn + base);
#pragma unroll
        for (int r = 0; r < 8; r++) {
            int f   = t + r * 256;
            int row = f >> 6, c4 = f & 63;
            float nq = NRM[row], nk = NRM[32 + row], be = BET[row];
            float4 xq = *(float4*)&Q[row * P1S + c4 * 4];
            xq.x *= nq; xq.y *= nq; xq.z *= nq; xq.w *= nq;
            *(float4*)&Q[row * P1S + c4 * 4] = xq;
            oq[f] = xq;
            float4 xk = *(float4*)&K[row * P1S + c4 * 4];
            xk.x *= nk; xk.y *= nk; xk.z *= nk; xk.w *= nk;
            *(float4*)&K[row * P1S + c4 * 4] = xk;
            ok[f] = xk;
            float4 xv = *(float4*)&V[row * P1S + c4 * 4];
            xv.x *= be; xv.y *= be; xv.z *= be; xv.w *= be;
            *(float4*)&V[row * P1S + c4 * 4] = xv;
        }
    }
    __syncthreads();

    // A (strict lower, beta_i * kn_i . kn_j) and att (tril incl diag).
    {
        const int w8 = t >> 5, la = t & 31;
        const int i  = w8 * 4 + (la >> 3);
        const int jq = la & 7;
        float dkk0 = 0.f, dkk1 = 0.f, dkk2 = 0.f, dkk3 = 0.f;
        float dqk0 = 0.f, dqk1 = 0.f, dqk2 = 0.f, dqk3 = 0.f;
        const float* Ki = &K[i * P1S];
        const float* Qi = &Q[i * P1S];
        const float* Kj0 = &K[(jq     ) * P1S];
        const float* Kj1 = &K[(jq +  8) * P1S];
        const float* Kj2 = &K[(jq + 16) * P1S];
        const float* Kj3 = &K[(jq + 24) * P1S];
#pragma unroll 8
        for (int d4 = 0; d4 < 64; d4++) {
            float4 ki = *(const float4*)&Ki[d4 * 4];
            float4 qi = *(const float4*)&Qi[d4 * 4];
            float4 a0 = *(const float4*)&Kj0[d4 * 4];
            float4 a1 = *(const float4*)&Kj1[d4 * 4];
            float4 a2 = *(const float4*)&Kj2[d4 * 4];
            float4 a3 = *(const float4*)&Kj3[d4 * 4];
            dkk0 += ki.x*a0.x + ki.y*a0.y + ki.z*a0.z + ki.w*a0.w;
            dkk1 += ki.x*a1.x + ki.y*a1.y + ki.z*a1.z + ki.w*a1.w;
            dkk2 += ki.x*a2.x + ki.y*a2.y + ki.z*a2.z + ki.w*a2.w;
            dkk3 += ki.x*a3.x + ki.y*a3.y + ki.z*a3.z + ki.w*a3.w;
            dqk0 += qi.x*a0.x + qi.y*a0.y + qi.z*a0.z + qi.w*a0.w;
            dqk1 += qi.x*a1.x + qi.y*a1.y + qi.z*a1.z + qi.w*a1.w;
            dqk2 += qi.x*a2.x + qi.y*a2.y + qi.z*a2.z + qi.w*a2.w;
            dqk3 += qi.x*a3.x + qi.y*a3.y + qi.z*a3.z + qi.w*a3.w;
        }
        float bi = BET[i];
        float* attg = g_att + ((size_t)(bh * NCH + ch)) * (CCH * CCH) + i * 32;
        int j;
        j = jq;      A[i*36+j] = (j <  i) ? bi*dkk0 : 0.f; attg[j] = (j <= i) ? dqk0 : 0.f;
        j = jq + 8;  A[i*36+j] = (j <  i) ? bi*dkk1 : 0.f; attg[j] = (j <= i) ? dqk1 : 0.f;
        j = jq + 16; A[i*36+j] = (j <  i) ? bi*dkk2 : 0.f; attg[j] = (j <= i) ? dqk2 : 0.f;
        j = jq + 24; A[i*36+j] = (j <  i) ? bi*dkk3 : 0.f; attg[j] = (j <= i) ? dqk3 : 0.f;
    }
    __syncthreads();

    // Forward substitution, register-resident per column (no barriers).
    {
        float rk[32], rv[32];
        float* ow = g_w + base + t;
        float* ou = g_u + base + t;
#pragma unroll
        for (int i = 0; i < 32; i++) {
            float accw = BET[i] * K[i * P1S + t];
            float accv = V[i * P1S + t];
            const int i4 = i >> 2;
#pragma unroll
            for (int b = 0; b < i4; b++) {
                float4 a = *(const float4*)&A[i * 36 + b * 4];
                accw -= a.x * rk[b*4+0] + a.y * rk[b*4+1]
                      + a.z * rk[b*4+2] + a.w * rk[b*4+3];
                accv -= a.x * rv[b*4+0] + a.y * rv[b*4+1]
                      + a.z * rv[b*4+2] + a.w * rv[b*4+3];
            }
#pragma unroll
            for (int j = i4 * 4; j < i; j++) {
                float a = A[i * 36 + j];
                accw -= a * rk[j];
                accv -= a * rv[j];
            }
            rk[i] = accw;
            rv[i] = accv;
            ow[(size_t)i * DKV] = accw;
            ou[(size_t)i * DKV] = accv;
        }
    }
}

// ============================================================================
// Phase 2: sequential scan over chunks. Grid = (NJB, BHT) = 128 CTAs, 512 thr.
// GEMM-A: 2x4 register tile, 4-way d split. GEMM-C: 4j x 4d per-thread tile
// (K: 1 wavefront/i instead of 4 broadcasts; UADJ: 1 float4/i).
// S swizzle key = (j>>2)&7 throughout.
// ============================================================================
#define P2S 260

__global__ __launch_bounds__(512, 1)
void phase2(float* __restrict__ out, int write_state)
{
    const int jb = blockIdx.x;
    const int bh = blockIdx.y;
    extern __shared__ float sm[];
    float* Wt   = sm;                          // 32 * 260
    float* Qt   = Wt + 32 * P2S;
    float* Kt   = Qt + 32 * P2S;
    float* St   = Kt + 32 * P2S;               // 32 * 256 (S^T, swizzled key=(j>>2)&7)
    float* Usl0 = St + 32 * 256;               // 32 * 36 each below
    float* Usl1 = Usl0 + 32 * 36;
    float* ATT0 = Usl1 + 32 * 36;
    float* ATT1 = ATT0 + 32 * 36;
    float* WSp  = ATT1 + 32 * 36;              // 4 partial buffers (d-slices)
    float* QSp  = WSp  + 4 * 32 * 36;          // 4 partial buffers
    float* UADJ = QSp  + 4 * 32 * 36;

    const int t = threadIdx.x;

    // zero S
#pragma unroll
    for (int r = 0; r < 16; r++) St[t + r * 512] = 0.f;

    // GEMM-A map: 2x4 (i,j) tile; 4 d-slices; warp covers 4 ip x 8 jq
    const int quarter = t >> 7;                // d-slice 0..3
    const int r128 = t & 127;
    const int w4 = r128 >> 5, la = r128 & 31;
    const int ip = (w4 << 2) | (la >> 3);      // 0..15
    const int jq = la & 7;                     // 0..7 (j0 = 4*jq, 4 consecutive)
    const int i0 = 2 * ip, i1 = i0 + 1;
    const int j0 = 4 * jq;
    const int d4base = quarter << 4;           // 16 d4-steps per slice
    float* WSq = WSp + quarter * (32 * 36);
    float* QSq = QSp + quarter * (32 * 36);
    // GEMM-C map: thread owns 4 j rows (j0c..j0c+3) x one 16B d-chunk dg16
    const int jq4c = t & 7;                    // j0c = 4*jq4c
    const int dg16 = t >> 3;                   // 0..63 (16B chunk index in d)
    const int j0c  = 4 * jq4c;
    const int keyCC = jq4c;                    // ((j0c+m)>>2)&7 == jq4c
    // epilogue/merge map (512 threads, float2)
    const int ei = t >> 4, ej2 = (t & 15) * 2;

    const size_t bh_base  = (size_t)bh * LSEQ * DKV;
    const size_t att_base = (size_t)(bh * NCH) * 1024;

    // ---- prime pipeline: load chunk 0 tiles ----
    {
        const size_t base = bh_base;   // ch = 0
        const float4* w4p = (const float4*)(g_w + base);
        const float4* q4p = (const float4*)(g_qn + base);
        const float4* k4p = (const float4*)(g_kn + base);
#pragma unroll
        for (int r = 0; r < 4; r++) {
            int f   = t + r * 512;
            int row = f >> 6, c4 = f & 63;
            cpa16(&Wt[row * P2S + c4 * 4], &w4p[f]);
            cpa16(&Qt[row * P2S + c4 * 4], &q4p[f]);
            cpa16(&Kt[row * P2S + c4 * 4], &k4p[f]);
        }
        if (t < 256) {
            int li = t >> 3, lj4 = (t & 7) * 4;
            cpa16(&Usl0[li * 36 + lj4], &g_u[base + (size_t)li * DKV + jb * JBW + lj4]);
            cpa16(&ATT0[li * 36 + lj4], &g_att[att_base + li * 32 + lj4]);
        }
        cpa_commit();
    }

    for (int ch = 0; ch < NCH; ch++) {
        const int p = ch & 1;
        float* Usl  = p ? Usl1 : Usl0;
        float* ATTs = p ? ATT1 : ATT0;
        float* UslN = p ? Usl0 : Usl1;
        float* ATTN = p ? ATT0 : ATT1;

        cpa_wait_all();
        __syncthreads();

        // ---- GEMM A: WS = w @ S, QS = q @ S  (f32x2, 2x4 tile, 4 d-slices) ----
        {
            unsigned long long wa[2][4], qa[2][4];
#pragma unroll
            for (int a = 0; a < 2; a++)
#pragma unroll
                for (int b = 0; b < 4; b++) { wa[a][b] = 0; qa[a][b] = 0; }

            const ulonglong2* wr0 = (const ulonglong2*)&Wt[i0 * P2S];
            const ulonglong2* wr1 = (const ulonglong2*)&Wt[i1 * P2S];
            const ulonglong2* qr0 = (const ulonglong2*)&Qt[i0 * P2S];
            const ulonglong2* qr1 = (const ulonglong2*)&Qt[i1 * P2S];
            const float* sr0 = &St[(j0 + 0) * 256];
            const float* sr1 = &St[(j0 + 1) * 256];
            const float* sr2 = &St[(j0 + 2) * 256];
            const float* sr3 = &St[(j0 + 3) * 256];
#pragma unroll 2
            for (int d4r = 0; d4r < 16; d4r++) {
                int d4 = d4base + d4r;
                int u  = (d4 ^ jq) << 2;
                ulonglong2 wv0 = wr0[d4];
                ulonglong2 wv1 = wr1[d4];
                ulonglong2 qv0 = qr0[d4];
                ulonglong2 qv1 = qr1[d4];
                ulonglong2 sv0 = *(const ulonglong2*)&sr0[u];
                ulonglong2 sv1 = *(const ulonglong2*)&sr1[u];
                ulonglong2 sv2 = *(const ulonglong2*)&sr2[u];
                ulonglong2 sv3 = *(const ulonglong2*)&sr3[u];
                wa[0][0] = ffma2(wv0.x, sv0.x, wa[0][0]); wa[0][0] = ffma2(wv0.y, sv0.y, wa[0][0]);
                wa[0][1] = ffma2(wv0.x, sv1.x, wa[0][1]); wa[0][1] = ffma2(wv0.y, sv1.y, wa[0][1]);
                wa[0][2] = ffma2(wv0.x, sv2.x, wa[0][2]); wa[0][2] = ffma2(wv0.y, sv2.y, wa[0][2]);
                wa[0][3] = ffma2(wv0.x, sv3.x, wa[0][3]); wa[0][3] = ffma2(wv0.y, sv3.y, wa[0][3]);
                wa[1][0] = ffma2(wv1.x, sv0.x, wa[1][0]); wa[1][0] = ffma2(wv1.y, sv0.y, wa[1][0]);
                wa[1][1] = ffma2(wv1.x, sv1.x, wa[1][1]); wa[1][1] = ffma2(wv1.y, sv1.y, wa[1][1]);
                wa[1][2] = ffma2(wv1.x, sv2.x, wa[1][2]); wa[1][2] = ffma2(wv1.y, sv2.y, wa[1][2]);
                wa[1][3] = ffma2(wv1.x, sv3.x, wa[1][3]); wa[1][3] = ffma2(wv1.y, sv3.y, wa[1][3]);
                qa[0][0] = ffma2(qv0.x, sv0.x, qa[0][0]); qa[0][0] = ffma2(qv0.y, sv0.y, qa[0][0]);
                qa[0][1] = ffma2(qv0.x, sv1.x, qa[0][1]); qa[0][1] = ffma2(qv0.y, sv1.y, qa[0][1]);
                qa[0][2] = ffma2(qv0.x, sv2.x, qa[0][2]); qa[0][2] = ffma2(qv0.y, sv2.y, qa[0][2]);
                qa[0][3] = ffma2(qv0.x, sv3.x, qa[0][3]); qa[0][3] = ffma2(qv0.y, sv3.y, qa[0][3]);
                qa[1][0] = ffma2(qv1.x, sv0.x, qa[1][0]); qa[1][0] = ffma2(qv1.y, sv0.y, qa[1][0]);
                qa[1][1] = ffma2(qv1.x, sv1.x, qa[1][1]); qa[1][1] = ffma2(qv1.y, sv1.y, qa[1][1]);
                qa[1][2] = ffma2(qv1.x, sv2.x, qa[1][2]); qa[1][2] = ffma2(qv1.y, sv2.y, qa[1][2]);
                qa[1][3] = ffma2(qv1.x, sv3.x, qa[1][3]); qa[1][3] = ffma2(qv1.y, sv3.y, qa[1][3]);
            }
            float4 f;
            f.x = fold2(wa[0][0]); f.y = fold2(wa[0][1]);
            f.z = fold2(wa[0][2]); f.w = fold2(wa[0][3]);
            *(float4*)&WSq[i0 * 36 + j0] = f;
            f.x = fold2(wa[1][0]); f.y = fold2(wa[1][1]);
            f.z = fold2(wa[1][2]); f.w = fold2(wa[1][3]);
            *(float4*)&WSq[i1 * 36 + j0] = f;
            f.x = fold2(qa[0][0]); f.y = fold2(qa[0][1]);
            f.z = fold2(qa[0][2]); f.w = fold2(qa[0][3]);
            *(float4*)&QSq[i0 * 36 + j0] = f;
            f.x = fold2(qa[1][0]); f.y = fold2(qa[1][1]);
            f.z = fold2(qa[1][2]); f.w = fold2(qa[1][3]);
            *(float4*)&QSq[i1 * 36 + j0] = f;
        }
        __syncthreads();

        // ---- GEMM-C S preload (St stable now) overlapping UADJ pass ----
        ulonglong2 sa[4];
        {
#pragma unroll
            for (int m = 0; m < 4; m++)
                sa[m] = *(const ulonglong2*)&St[(j0c + m) * 256 + ((dg16 ^ keyCC) << 2)];
        }

        // ---- UADJ = u - sum of 4 WS partials (512 threads, float2) ----
        {
            float2 uu = *(float2*)&Usl[ei * 36 + ej2];
            float2 w0 = *(float2*)&WSp[0 * 32 * 36 + ei * 36 + ej2];
            float2 w1 = *(float2*)&WSp[1 * 32 * 36 + ei * 36 + ej2];
            float2 w2 = *(float2*)&WSp[2 * 32 * 36 + ei * 36 + ej2];
            float2 w3 = *(float2*)&WSp[3 * 32 * 36 + ei * 36 + ej2];
            float2 r;
            r.x = uu.x - w0.x - w1.x - w2.x - w3.x;
            r.y = uu.y - w0.y - w1.y - w2.y - w3.y;
            *(float2*)&UADJ[ei * 36 + ej2] = r;
        }
        __syncthreads();

        // ---- prefetch next chunk's W/Q tiles + usl/att (Wt/Qt now dead) ----
        if (ch + 1 < NCH) {
            const size_t nbase = bh_base + (size_t)(ch + 1) * CCH * DKV;
            const float4* w4p = (const float4*)(g_w + nbase);
            const float4* q4p = (const float4*)(g_qn + nbase);
#pragma unroll
            for (int r = 0; r < 4; r++) {
                int f   = t + r * 512;
                int row = f >> 6, c4 = f & 63;
                cpa16(&Wt[row * P2S + c4 * 4], &w4p[f]);
                cpa16(&Qt[row * P2S + c4 * 4], &q4p[f]);
            }
            if (t < 256) {
                int li = t >> 3, lj4 = (t & 7) * 4;
                cpa16(&UslN[li * 36 + lj4],
                      &g_u[nbase + (size_t)li * DKV + jb * JBW + lj4]);
                cpa16(&ATTN[li * 36 + lj4],
                      &g_att[att_base + (size_t)(ch + 1) * 1024 + li * 32 + lj4]);
            }
            cpa_commit();
        }

        // ---- GEMM C: S += k^T @ UADJ  (4j x 4d per thread) ----
        {
#pragma unroll 4
            for (int i = 0; i < CCH; i++) {
                float4 ua = *(const float4*)&UADJ[i * 36 + j0c];
                ulonglong2 kv = *(const ulonglong2*)&Kt[i * P2S + dg16 * 4];
                unsigned long long us0 = splat2(ua.x);
                unsigned long long us1 = splat2(ua.y);
                unsigned long long us2 = splat2(ua.z);
                unsigned long long us3 = splat2(ua.w);
                sa[0].x = ffma2(kv.x, us0, sa[0].x); sa[0].y = ffma2(kv.y, us0, sa[0].y);
                sa[1].x = ffma2(kv.x, us1, sa[1].x); sa[1].y = ffma2(kv.y, us1, sa[1].y);
                sa[2].x = ffma2(kv.x, us2, sa[2].x); sa[2].y = ffma2(kv.y, us2, sa[2].y);
                sa[3].x = ffma2(kv.x, us3, sa[3].x); sa[3].y = ffma2(kv.y, us3, sa[3].y);
            }
#pragma unroll
            for (int m = 0; m < 4; m++)
                *(ulonglong2*)&St[(j0c + m) * 256 + ((dg16 ^ keyCC) << 2)] = sa[m];
        }
        __syncthreads();

        // ---- prefetch next chunk's K tile (Kt now dead) ----
        if (ch + 1 < NCH) {
            const size_t nbase = bh_base + (size_t)(ch + 1) * CCH * DKV;
            const float4* k4p = (const float4*)(g_kn + nbase);
#pragma unroll
            for (int r = 0; r < 4; r++) {
                int f   = t + r * 512;
                int row = f >> 6, c4 = f & 63;
                cpa16(&Kt[row * P2S + c4 * 4], &k4p[f]);
            }
            cpa_commit();
        }

        // ---- O = sum QS + att @ UADJ ; write to global (512 threads, float2) ----
        {
            float2 q0 = *(float2*)&QSp[0 * 32 * 36 + ei * 36 + ej2];
            float2 q1 = *(float2*)&QSp[1 * 32 * 36 + ei * 36 + ej2];
            float2 q2 = *(float2*)&QSp[2 * 32 * 36 + ei * 36 + ej2];
            float2 q3 = *(float2*)&QSp[3 * 32 * 36 + ei * 36 + ej2];
            float2 o;
            o.x = (q0.x + q1.x) + (q2.x + q3.x);
            o.y = (q0.y + q1.y) + (q2.y + q3.y);
#pragma unroll 8
            for (int ii = 0; ii < CCH; ii++) {
                float a = ATTs[ei * 36 + ii];   // zero above diag
                float2 ub = *(float2*)&UADJ[ii * 36 + ej2];
                o.x += a * ub.x;
                o.y += a * ub.y;
            }
            *(float2*)&out[((size_t)bh * LSEQ + (size_t)ch * CCH + ei) * DKV +
                           jb * JBW + ej2] = o;
        }
        // no trailing barrier: loop-top wait + __syncthreads orders everything
    }

    // ---- final state S (second tuple element) ----
    if (write_state) {
        __syncthreads();
        const size_t soff = OUT_ELEMS;
#pragma unroll
        for (int m = 0; m < 4; m++) {
#pragma unroll
            for (int e = 0; e < 4; e++) {
                int d = dg16 * 4 + e;
                float val = St[(j0c + m) * 256 + ((dg16 ^ keyCC) << 2) + e];
                out[soff + ((size_t)bh * DKV + d) * DKV + jb * JBW + j0c + m] = val;
            }
        }
    }
}

// ============================================================================

#define SM1_BYTES ((32 * P1S * 3 + 32 * 36 + 512 + 32 + 64) * sizeof(float))
#define SM2_BYTES ((32 * P2S * 3 + 32 * 256 + 13 * 32 * 36) * sizeof(float))

extern "C" void kernel_launch(void* const* d_in, const int* in_sizes, int n_in,
                              void* d_out, int out_size)
{
    const float* q    = (const float*)d_in[0];
    const float* k    = (const float*)d_in[1];
    const float* v    = (const float*)d_in[2];
    const float* beta = (const float*)d_in[3];
    float* out = (float*)d_out;

    cudaFuncSetAttribute(phase1, cudaFuncAttributeMaxDynamicSharedMemorySize, SM1_BYTES);
    cudaFuncSetAttribute(phase2, cudaFuncAttributeMaxDynamicSharedMemorySize, SM2_BYTES);

    phase1<<<dim3(NCH, BHT), 256, SM1_BYTES>>>(q, k, v, beta);

    int ws = ((size_t)out_size >= OUT_ELEMS + STATE_ELEMS) ? 1 : 0;
    phase2<<<dim3(NJB, BHT), 512, SM2_BYTES>>>(out, ws);
}

// round 17
// speedup vs baseline: 1.5471x; 1.0307x over previous
#include <cuda_runtime.h>

// DeltaNet chunkwise delta rule.
// Shapes fixed by the problem: b=4, h=4, L=4096, dk=dv=256, chunk=32.

#define LSEQ  4096
#define DKV   256
#define CCH   32
#define NCH   (LSEQ / CCH)      // 128 chunks
#define BHT   16                // b*h
#define JBW   32                // dv block width in phase 2
#define NJB   (DKV / JBW)       // 8 column blocks

#define OUT_ELEMS   ((size_t)BHT * LSEQ * DKV)        // 16777216
#define STATE_ELEMS ((size_t)BHT * DKV * DKV)         // 1048576

// Scratch (device globals; no allocation allowed)
__device__ float g_qn [(size_t)BHT * LSEQ * DKV];
__device__ float g_kn [(size_t)BHT * LSEQ * DKV];
__device__ float g_w  [(size_t)BHT * LSEQ * DKV];
__device__ float g_u  [(size_t)BHT * LSEQ * DKV];
__device__ float g_att[(size_t)BHT * NCH * CCH * CCH];

// ---- packed f32x2 helpers (2x FFMA throughput vs 3-reg FFMA on sm_103a) ----
__device__ __forceinline__ unsigned long long ffma2(unsigned long long a,
                                                    unsigned long long b,
                                                    unsigned long long c) {
    unsigned long long d;
    asm("fma.rn.f32x2 %0, %1, %2, %3;" : "=l"(d) : "l"(a), "l"(b), "l"(c));
    return d;
}
__device__ __forceinline__ unsigned long long splat2(float x) {
    unsigned long long d;
    unsigned int r = __float_as_uint(x);
    asm("mov.b64 %0, {%1, %1};" : "=l"(d) : "r"(r));
    return d;
}
__device__ __forceinline__ float fold2(unsigned long long a) {
    unsigned int lo, hi;
    asm("mov.b64 {%0, %1}, %2;" : "=r"(lo), "=r"(hi) : "l"(a));
    return __uint_as_float(lo) + __uint_as_float(hi);
}

// ---- cp.async: global -> shared 16B, no register round-trip ----
__device__ __forceinline__ void cpa16(void* smem_dst, const void* gmem_src) {
    unsigned int s = (unsigned int)__cvta_generic_to_shared(smem_dst);
    asm volatile("cp.async.ca.shared.global [%0], [%1], 16;" :: "r"(s), "l"(gmem_src));
}
__device__ __forceinline__ void cpa_commit() {
    asm volatile("cp.async.commit_group;");
}
__device__ __forceinline__ void cpa_wait_all() {
    asm volatile("cp.async.wait_group 0;" ::: "memory");
}

// ============================================================================
// Phase 1: per-chunk preprocessing (parallel over bh * chunks = 2048 CTAs).
// ============================================================================
#define P1S 260

__global__ __launch_bounds__(256, 2)
void phase1(const float* __restrict__ q, const float* __restrict__ k,
            const float* __restrict__ v, const float* __restrict__ beta)
{
    const int ch = blockIdx.x;
    const int bh = blockIdx.y;
    extern __shared__ float sm[];
    float* Q   = sm;                         // 32 * 260
    float* K   = Q + 32 * P1S;
    float* V   = K + 32 * P1S;
    float* A   = V + 32 * P1S;               // 32 * 36
    float* RED = A + 32 * 36;                // 512
    float* BET = RED + 512;                  // 32
    float* NRM = BET + 32;                   // 64

    const int t = threadIdx.x;
    const size_t base = ((size_t)bh * LSEQ + (size_t)ch * CCH) * DKV;
    const float4* q4 = (const float4*)(q + base);
    const float4* k4 = (const float4*)(k + base);
    const float4* v4 = (const float4*)(v + base);

#pragma unroll
    for (int r = 0; r < 8; r++) {
        int f   = t + r * 256;
        int row = f >> 6, c4 = f & 63;
        cpa16(&Q[row * P1S + c4 * 4], &q4[f]);
        cpa16(&K[row * P1S + c4 * 4], &k4[f]);
        cpa16(&V[row * P1S + c4 * 4], &v4[f]);
    }
    if (t < CCH) BET[t] = beta[(size_t)bh * LSEQ + ch * CCH + t];
    cpa_commit();
    cpa_wait_all();
    __syncthreads();

    // row sum-of-squares for q and k
    {
        int r = t >> 3, s = t & 7;
        float aq = 0.f, ak = 0.f;
#pragma unroll
        for (int m = 0; m < 32; m++) {
            float xq = Q[r * P1S + s * 32 + m];
            float xk = K[r * P1S + s * 32 + m];
            aq += xq * xq;
            ak += xk * xk;
        }
        RED[r * 8 + s]       = aq;
        RED[256 + r * 8 + s] = ak;
    }
    __syncthreads();
    if (t < 64) {
        int r = t & 31, wsel = t >> 5;
        float ssum = 0.f;
#pragma unroll
        for (int s = 0; s < 8; s++) ssum += RED[wsel * 256 + r * 8 + s];
        NRM[t] = rsqrtf(ssum);
    }
    __syncthreads();

    // normalize q,k (write qn,kn straight to global) ; v *= beta
    {
        float4* oq = (float4*)(g_qn + base);
        float4* ok = (float4*)(g_kn + base);
#pragma unroll
        for (int r = 0; r < 8; r++) {
            int f   = t + r * 256;
            int row = f >> 6, c4 = f & 63;
            float nq = NRM[row], nk = NRM[32 + row], be = BET[row];
            float4 xq = *(float4*)&Q[row * P1S + c4 * 4];
            xq.x *= nq; xq.y *= nq; xq.z *= nq; xq.w *= nq;
            *(float4*)&Q[row * P1S + c4 * 4] = xq;
            oq[f] = xq;
            float4 xk = *(float4*)&K[row * P1S + c4 * 4];
            xk.x *= nk; xk.y *= nk; xk.z *= nk; xk.w *= nk;
            *(float4*)&K[row * P1S + c4 * 4] = xk;
            ok[f] = xk;
            float4 xv = *(float4*)&V[row * P1S + c4 * 4];
            xv.x *= be; xv.y *= be; xv.z *= be; xv.w *= be;
            *(float4*)&V[row * P1S + c4 * 4] = xv;
        }
    }
    __syncthreads();

    // A (strict lower, beta_i * kn_i . kn_j) and att (tril incl diag).
    {
        const int w8 = t >> 5, la = t & 31;
        const int i  = w8 * 4 + (la >> 3);
        const int jq = la & 7;
        float dkk0 = 0.f, dkk1 = 0.f, dkk2 = 0.f, dkk3 = 0.f;
        float dqk0 = 0.f, dqk1 = 0.f, dqk2 = 0.f, dqk3 = 0.f;
        const float* Ki = &K[i * P1S];
        const float* Qi = &Q[i * P1S];
        const float* Kj0 = &K[(jq     ) * P1S];
        const float* Kj1 = &K[(jq +  8) * P1S];
        const float* Kj2 = &K[(jq + 16) * P1S];
        const float* Kj3 = &K[(jq + 24) * P1S];
#pragma unroll 8
        for (int d4 = 0; d4 < 64; d4++) {
            float4 ki = *(const float4*)&Ki[d4 * 4];
            float4 qi = *(const float4*)&Qi[d4 * 4];
            float4 a0 = *(const float4*)&Kj0[d4 * 4];
            float4 a1 = *(const float4*)&Kj1[d4 * 4];
            float4 a2 = *(const float4*)&Kj2[d4 * 4];
            float4 a3 = *(const float4*)&Kj3[d4 * 4];
            dkk0 += ki.x*a0.x + ki.y*a0.y + ki.z*a0.z + ki.w*a0.w;
            dkk1 += ki.x*a1.x + ki.y*a1.y + ki.z*a1.z + ki.w*a1.w;
            dkk2 += ki.x*a2.x + ki.y*a2.y + ki.z*a2.z + ki.w*a2.w;
            dkk3 += ki.x*a3.x + ki.y*a3.y + ki.z*a3.z + ki.w*a3.w;
            dqk0 += qi.x*a0.x + qi.y*a0.y + qi.z*a0.z + qi.w*a0.w;
            dqk1 += qi.x*a1.x + qi.y*a1.y + qi.z*a1.z + qi.w*a1.w;
            dqk2 += qi.x*a2.x + qi.y*a2.y + qi.z*a2.z + qi.w*a2.w;
            dqk3 += qi.x*a3.x + qi.y*a3.y + qi.z*a3.z + qi.w*a3.w;
        }
        float bi = BET[i];
        float* attg = g_att + ((size_t)(bh * NCH + ch)) * (CCH * CCH) + i * 32;
        int j;
        j = jq;      A[i*36+j] = (j <  i) ? bi*dkk0 : 0.f; attg[j] = (j <= i) ? dqk0 : 0.f;
        j = jq + 8;  A[i*36+j] = (j <  i) ? bi*dkk1 : 0.f; attg[j] = (j <= i) ? dqk1 : 0.f;
        j = jq + 16; A[i*36+j] = (j <  i) ? bi*dkk2 : 0.f; attg[j] = (j <= i) ? dqk2 : 0.f;
        j = jq + 24; A[i*36+j] = (j <  i) ? bi*dkk3 : 0.f; attg[j] = (j <= i) ? dqk3 : 0.f;
    }
    __syncthreads();

    // Forward substitution, register-resident per column (no barriers).
    {
        float rk[32], rv[32];
        float* ow = g_w + base + t;
        float* ou = g_u + base + t;
#pragma unroll
        for (int i = 0; i < 32; i++) {
            float accw = BET[i] * K[i * P1S + t];
            float accv = V[i * P1S + t];
            const int i4 = i >> 2;
#pragma unroll
            for (int b = 0; b < i4; b++) {
                float4 a = *(const float4*)&A[i * 36 + b * 4];
                accw -= a.x * rk[b*4+0] + a.y * rk[b*4+1]
                      + a.z * rk[b*4+2] + a.w * rk[b*4+3];
                accv -= a.x * rv[b*4+0] + a.y * rv[b*4+1]
                      + a.z * rv[b*4+2] + a.w * rv[b*4+3];
            }
#pragma unroll
            for (int j = i4 * 4; j < i; j++) {
                float a = A[i * 36 + j];
                accw -= a * rk[j];
                accv -= a * rv[j];
            }
            rk[i] = accw;
            rv[i] = accv;
            ow[(size_t)i * DKV] = accw;
            ou[(size_t)i * DKV] = accv;
        }
    }
}

// ============================================================================
// Phase 2: sequential scan over chunks. Grid = (NJB, BHT) = 128 CTAs, 512 thr.
// GEMM-A: 2x4 register tile, 4-way d split. GEMM-C: 4j x 4d per-thread tile.
// Epilogue: 2x4 tile, ii split across quarters, accumulated IN PLACE into the
// QS partial buffers (triangular warp-uniform skip), then a thin merge pass.
// S swizzle key = (j>>2)&7 throughout.
// ============================================================================
#define P2S 260

__global__ __launch_bounds__(512, 1)
void phase2(float* __restrict__ out, int write_state)
{
    const int jb = blockIdx.x;
    const int bh = blockIdx.y;
    extern __shared__ float sm[];
    float* Wt   = sm;                          // 32 * 260
    float* Qt   = Wt + 32 * P2S;
    float* Kt   = Qt + 32 * P2S;
    float* St   = Kt + 32 * P2S;               // 32 * 256 (S^T, swizzled key=(j>>2)&7)
    float* Usl0 = St + 32 * 256;               // 32 * 36 each below
    float* Usl1 = Usl0 + 32 * 36;
    float* ATT0 = Usl1 + 32 * 36;
    float* ATT1 = ATT0 + 32 * 36;
    float* WSp  = ATT1 + 32 * 36;              // 4 partial buffers (d-slices)
    float* QSp  = WSp  + 4 * 32 * 36;          // 4 partial buffers -> O partials
    float* UADJ = QSp  + 4 * 32 * 36;

    const int t = threadIdx.x;

    // zero S
#pragma unroll
    for (int r = 0; r < 16; r++) St[t + r * 512] = 0.f;

    // GEMM-A map: 2x4 (i,j) tile; 4 d-slices; warp covers 4 ip x 8 jq
    const int quarter = t >> 7;                // d-slice / ii-slice 0..3
    const int r128 = t & 127;
    const int w4 = r128 >> 5, la = r128 & 31;
    const int ip = (w4 << 2) | (la >> 3);      // 0..15
    const int jq = la & 7;                     // 0..7 (j0 = 4*jq, 4 consecutive)
    const int i0 = 2 * ip, i1 = i0 + 1;
    const int j0 = 4 * jq;
    const int d4base = quarter << 4;           // 16 d4-steps per slice
    float* WSq = WSp + quarter * (32 * 36);
    float* QSq = QSp + quarter * (32 * 36);
    // GEMM-C map: thread owns 4 j rows (j0c..j0c+3) x one 16B d-chunk dg16
    const int jq4c = t & 7;                    // j0c = 4*jq4c
    const int dg16 = t >> 3;                   // 0..63 (16B chunk index in d)
    const int j0c  = 4 * jq4c;
    const int keyCC = jq4c;                    // ((j0c+m)>>2)&7 == jq4c
    // UADJ / merge map (512 threads, float2)
    const int ei = t >> 4, ej2 = (t & 15) * 2;

    const size_t bh_base  = (size_t)bh * LSEQ * DKV;
    const size_t att_base = (size_t)(bh * NCH) * 1024;

    // ---- prime pipeline: load chunk 0 tiles ----
    {
        const size_t base = bh_base;   // ch = 0
        const float4* w4p = (const float4*)(g_w + base);
        const float4* q4p = (const float4*)(g_qn + base);
        const float4* k4p = (const float4*)(g_kn + base);
#pragma unroll
        for (int r = 0; r < 4; r++) {
            int f   = t + r * 512;
            int row = f >> 6, c4 = f & 63;
            cpa16(&Wt[row * P2S + c4 * 4], &w4p[f]);
            cpa16(&Qt[row * P2S + c4 * 4], &q4p[f]);
            cpa16(&Kt[row * P2S + c4 * 4], &k4p[f]);
        }
        if (t < 256) {
            int li = t >> 3, lj4 = (t & 7) * 4;
            cpa16(&Usl0[li * 36 + lj4], &g_u[base + (size_t)li * DKV + jb * JBW + lj4]);
            cpa16(&ATT0[li * 36 + lj4], &g_att[att_base + li * 32 + lj4]);
        }
        cpa_commit();
    }

    for (int ch = 0; ch < NCH; ch++) {
        const int p = ch & 1;
        float* Usl  = p ? Usl1 : Usl0;
        float* ATTs = p ? ATT1 : ATT0;
        float* UslN = p ? Usl0 : Usl1;
        float* ATTN = p ? ATT0 : ATT1;

        cpa_wait_all();
        __syncthreads();

        // ---- GEMM A: WS = w @ S, QS = q @ S  (f32x2, 2x4 tile, 4 d-slices) ----
        {
            unsigned long long wa[2][4], qa[2][4];
#pragma unroll
            for (int a = 0; a < 2; a++)
#pragma unroll
                for (int b = 0; b < 4; b++) { wa[a][b] = 0; qa[a][b] = 0; }

            const ulonglong2* wr0 = (const ulonglong2*)&Wt[i0 * P2S];
            const ulonglong2* wr1 = (const ulonglong2*)&Wt[i1 * P2S];
            const ulonglong2* qr0 = (const ulonglong2*)&Qt[i0 * P2S];
            const ulonglong2* qr1 = (const ulonglong2*)&Qt[i1 * P2S];
            const float* sr0 = &St[(j0 + 0) * 256];
            const float* sr1 = &St[(j0 + 1) * 256];
            const float* sr2 = &St[(j0 + 2) * 256];
            const float* sr3 = &St[(j0 + 3) * 256];
#pragma unroll 2
            for (int d4r = 0; d4r < 16; d4r++) {
                int d4 = d4base + d4r;
                int u  = (d4 ^ jq) << 2;
                ulonglong2 wv0 = wr0[d4];
                ulonglong2 wv1 = wr1[d4];
                ulonglong2 qv0 = qr0[d4];
                ulonglong2 qv1 = qr1[d4];
                ulonglong2 sv0 = *(const ulonglong2*)&sr0[u];
                ulonglong2 sv1 = *(const ulonglong2*)&sr1[u];
                ulonglong2 sv2 = *(const ulonglong2*)&sr2[u];
                ulonglong2 sv3 = *(const ulonglong2*)&sr3[u];
                wa[0][0] = ffma2(wv0.x, sv0.x, wa[0][0]); wa[0][0] = ffma2(wv0.y, sv0.y, wa[0][0]);
                wa[0][1] = ffma2(wv0.x, sv1.x, wa[0][1]); wa[0][1] = ffma2(wv0.y, sv1.y, wa[0][1]);
                wa[0][2] = ffma2(wv0.x, sv2.x, wa[0][2]); wa[0][2] = ffma2(wv0.y, sv2.y, wa[0][2]);
                wa[0][3] = ffma2(wv0.x, sv3.x, wa[0][3]); wa[0][3] = ffma2(wv0.y, sv3.y, wa[0][3]);
                wa[1][0] = ffma2(wv1.x, sv0.x, wa[1][0]); wa[1][0] = ffma2(wv1.y, sv0.y, wa[1][0]);
                wa[1][1] = ffma2(wv1.x, sv1.x, wa[1][1]); wa[1][1] = ffma2(wv1.y, sv1.y, wa[1][1]);
                wa[1][2] = ffma2(wv1.x, sv2.x, wa[1][2]); wa[1][2] = ffma2(wv1.y, sv2.y, wa[1][2]);
                wa[1][3] = ffma2(wv1.x, sv3.x, wa[1][3]); wa[1][3] = ffma2(wv1.y, sv3.y, wa[1][3]);
                qa[0][0] = ffma2(qv0.x, sv0.x, qa[0][0]); qa[0][0] = ffma2(qv0.y, sv0.y, qa[0][0]);
                qa[0][1] = ffma2(qv0.x, sv1.x, qa[0][1]); qa[0][1] = ffma2(qv0.y, sv1.y, qa[0][1]);
                qa[0][2] = ffma2(qv0.x, sv2.x, qa[0][2]); qa[0][2] = ffma2(qv0.y, sv2.y, qa[0][2]);
                qa[0][3] = ffma2(qv0.x, sv3.x, qa[0][3]); qa[0][3] = ffma2(qv0.y, sv3.y, qa[0][3]);
                qa[1][0] = ffma2(qv1.x, sv0.x, qa[1][0]); qa[1][0] = ffma2(qv1.y, sv0.y, qa[1][0]);
                qa[1][1] = ffma2(qv1.x, sv1.x, qa[1][1]); qa[1][1] = ffma2(qv1.y, sv1.y, qa[1][1]);
                qa[1][2] = ffma2(qv1.x, sv2.x, qa[1][2]); qa[1][2] = ffma2(qv1.y, sv2.y, qa[1][2]);
                qa[1][3] = ffma2(qv1.x, sv3.x, qa[1][3]); qa[1][3] = ffma2(qv1.y, sv3.y, qa[1][3]);
            }
            float4 f;
            f.x = fold2(wa[0][0]); f.y = fold2(wa[0][1]);
            f.z = fold2(wa[0][2]); f.w = fold2(wa[0][3]);
            *(float4*)&WSq[i0 * 36 + j0] = f;
            f.x = fold2(wa[1][0]); f.y = fold2(wa[1][1]);
            f.z = fold2(wa[1][2]); f.w = fold2(wa[1][3]);
            *(float4*)&WSq[i1 * 36 + j0] = f;
            f.x = fold2(qa[0][0]); f.y = fold2(qa[0][1]);
            f.z = fold2(qa[0][2]); f.w = fold2(qa[0][3]);
            *(float4*)&QSq[i0 * 36 + j0] = f;
            f.x = fold2(qa[1][0]); f.y = fold2(qa[1][1]);
            f.z = fold2(qa[1][2]); f.w = fold2(qa[1][3]);
            *(float4*)&QSq[i1 * 36 + j0] = f;
        }
        __syncthreads();

        // ---- GEMM-C S preload (St stable now) overlapping UADJ pass ----
        ulonglong2 sa[4];
        {
#pragma unroll
            for (int m = 0; m < 4; m++)
                sa[m] = *(const ulonglong2*)&St[(j0c + m) * 256 + ((dg16 ^ keyCC) << 2)];
        }

        // ---- UADJ = u - sum of 4 WS partials (512 threads, float2) ----
        {
            float2 uu = *(float2*)&Usl[ei * 36 + ej2];
            float2 w0 = *(float2*)&WSp[0 * 32 * 36 + ei * 36 + ej2];
            float2 w1 = *(float2*)&WSp[1 * 32 * 36 + ei * 36 + ej2];
            float2 w2 = *(float2*)&WSp[2 * 32 * 36 + ei * 36 + ej2];
            float2 w3 = *(float2*)&WSp[3 * 32 * 36 + ei * 36 + ej2];
            float2 r;
            r.x = uu.x - w0.x - w1.x - w2.x - w3.x;
            r.y = uu.y - w0.y - w1.y - w2.y - w3.y;
            *(float2*)&UADJ[ei * 36 + ej2] = r;
        }
        __syncthreads();

        // ---- prefetch next chunk's W/Q tiles + usl/att (Wt/Qt now dead) ----
        if (ch + 1 < NCH) {
            const size_t nbase = bh_base + (size_t)(ch + 1) * CCH * DKV;
            const float4* w4p = (const float4*)(g_w + nbase);
            const float4* q4p = (const float4*)(g_qn + nbase);
#pragma unroll
            for (int r = 0; r < 4; r++) {
                int f   = t + r * 512;
                int row = f >> 6, c4 = f & 63;
                cpa16(&Wt[row * P2S + c4 * 4], &w4p[f]);
                cpa16(&Qt[row * P2S + c4 * 4], &q4p[f]);
            }
            if (t < 256) {
                int li = t >> 3, lj4 = (t & 7) * 4;
                cpa16(&UslN[li * 36 + lj4],
                      &g_u[nbase + (size_t)li * DKV + jb * JBW + lj4]);
                cpa16(&ATTN[li * 36 + lj4],
                      &g_att[att_base + (size_t)(ch + 1) * 1024 + li * 32 + lj4]);
            }
            cpa_commit();
        }

        // ---- GEMM C: S += k^T @ UADJ  (4j x 4d per thread) ----
        {
#pragma unroll 4
            for (int i = 0; i < CCH; i++) {
                float4 ua = *(const float4*)&UADJ[i * 36 + j0c];
                ulonglong2 kv = *(const ulonglong2*)&Kt[i * P2S + dg16 * 4];
                unsigned long long us0 = splat2(ua.x);
                unsigned long long us1 = splat2(ua.y);
                unsigned long long us2 = splat2(ua.z);
                unsigned long long us3 = splat2(ua.w);
                sa[0].x = ffma2(kv.x, us0, sa[0].x); sa[0].y = ffma2(kv.y, us0, sa[0].y);
                sa[1].x = ffma2(kv.x, us1, sa[1].x); sa[1].y = ffma2(kv.y, us1, sa[1].y);
                sa[2].x = ffma2(kv.x, us2, sa[2].x); sa[2].y = ffma2(kv.y, us2, sa[2].y);
                sa[3].x = ffma2(kv.x, us3, sa[3].x); sa[3].y = ffma2(kv.y, us3, sa[3].y);
            }
#pragma unroll
            for (int m = 0; m < 4; m++)
                *(ulonglong2*)&St[(j0c + m) * 256 + ((dg16 ^ keyCC) << 2)] = sa[m];
        }
        __syncthreads();

        // ---- prefetch next chunk's K tile (Kt now dead) ----
        if (ch + 1 < NCH) {
            const size_t nbase = bh_base + (size_t)(ch + 1) * CCH * DKV;
            const float4* k4p = (const float4*)(g_kn + nbase);
#pragma unroll
            for (int r = 0; r < 4; r++) {
                int f   = t + r * 512;
                int row = f >> 6, c4 = f & 63;
                cpa16(&Kt[row * P2S + c4 * 4], &k4p[f]);
            }
            cpa_commit();
        }

        // ---- partial epilogue: QSq += att @ UADJ over ii in [8q, 8q+8) ----
        // Output rows of warp w4 live in [8*w4, 8*w4+8); quarters q > w4
        // contribute only zeros (ATT upper triangle is stored as 0), so they
        // skip entirely (warp-uniform branch). QSq is updated in place.
        if (quarter <= w4) {
            float4 o0 = *(float4*)&QSq[i0 * 36 + j0];
            float4 o1 = *(float4*)&QSq[i1 * 36 + j0];
            const int iibase = quarter * 8;
#pragma unroll
            for (int r = 0; r < 8; r++) {
                int ii = iibase + r;
                float a0 = ATTs[i0 * 36 + ii];
                float a1 = ATTs[i1 * 36 + ii];
                float4 ub = *(const float4*)&UADJ[ii * 36 + j0];
                o0.x += a0 * ub.x; o0.y += a0 * ub.y;
                o0.z += a0 * ub.z; o0.w += a0 * ub.w;
                o1.x += a1 * ub.x; o1.y += a1 * ub.y;
                o1.z += a1 * ub.z; o1.w += a1 * ub.w;
            }
            *(float4*)&QSq[i0 * 36 + j0] = o0;
            *(float4*)&QSq[i1 * 36 + j0] = o1;
        }
        __syncthreads();

        // ---- merge: O = sum of 4 QS/O partials ; write to global ----
        {
            float2 q0 = *(float2*)&QSp[0 * 32 * 36 + ei * 36 + ej2];
            float2 q1 = *(float2*)&QSp[1 * 32 * 36 + ei * 36 + ej2];
            float2 q2 = *(float2*)&QSp[2 * 32 * 36 + ei * 36 + ej2];
            float2 q3 = *(float2*)&QSp[3 * 32 * 36 + ei * 36 + ej2];
            float2 o;
            o.x = (q0.x + q1.x) + (q2.x + q3.x);
            o.y = (q0.y + q1.y) + (q2.y + q3.y);
            *(float2*)&out[((size_t)bh * LSEQ + (size_t)ch * CCH + ei) * DKV +
                           jb * JBW + ej2] = o;
        }
        // no trailing barrier: loop-top wait + __syncthreads orders everything
    }

    // ---- final state S (second tuple element) ----
    if (write_state) {
        __syncthreads();
        const size_t soff = OUT_ELEMS;
#pragma unroll
        for (int m = 0; m < 4; m++) {
#pragma unroll
            for (int e = 0; e < 4; e++) {
                int d = dg16 * 4 + e;
                float val = St[(j0c + m) * 256 + ((dg16 ^ keyCC) << 2) + e];
                out[soff + ((size_t)bh * DKV + d) * DKV + jb * JBW + j0c + m] = val;
            }
        }
    }
}

// ============================================================================

#define SM1_BYTES ((32 * P1S * 3 + 32 * 36 + 512 + 32 + 64) * sizeof(float))
#define SM2_BYTES ((32 * P2S * 3 + 32 * 256 + 13 * 32 * 36) * sizeof(float))

extern "C" void kernel_launch(void* const* d_in, const int* in_sizes, int n_in,
                              void* d_out, int out_size)
{
    const float* q    = (const float*)d_in[0];
    const float* k    = (const float*)d_in[1];
    const float* v    = (const float*)d_in[2];
    const float* beta = (const float*)d_in[3];
    float* out = (float*)d_out;

    cudaFuncSetAttribute(phase1, cudaFuncAttributeMaxDynamicSharedMemorySize, SM1_BYTES);
    cudaFuncSetAttribute(phase2, cudaFuncAttributeMaxDynamicSharedMemorySize, SM2_BYTES);

    phase1<<<dim3(NCH, BHT), 256, SM1_BYTES>>>(q, k, v, beta);

    int ws = ((size_t)out_size >= OUT_ELEMS + STATE_ELEMS) ? 1 : 0;
    phase2<<<dim3(NJB, BHT), 512, SM2_BYTES>>>(out, ws);
}